// round 6
// baseline (speedup 1.0000x reference)
#include <cuda_runtime.h>
#include <cuda_bf16.h>
#include <math.h>

#define N_NODES 50000
#define N_PAD   50048            // 782 * 64
#define E_EDGES 800000
#define DIM     128
#define EDIM    32
#define HID     256
#define DEG     16
#define EPS     1e-5f

// ---------------- scratch (device globals; allocation-free rule) ------------
__device__ float g_S[N_NODES * HID];
__device__ float g_R[N_NODES * HID];
// packed activations: [kc][row][64 halves] = 32 hi || 32 lo  (128B per (kc,row))
__device__ __align__(16) __nv_bfloat16 g_nodeP [4ull * N_PAD * 64];
__device__ __align__(16) __nv_bfloat16 g_HaggP [8ull * N_PAD * 64];
__device__ __align__(16) __nv_bfloat16 g_agglnP[4ull * N_PAD * 64];
__device__ __align__(16) __nv_bfloat16 g_HP    [8ull * N_PAD * 64];
// packed weights: [kc][n][64 halves]
__device__ __align__(16) __nv_bfloat16 g_BP1  [4 * 512 * 64];   // [We1_top | We1_mid]
__device__ __align__(16) __nv_bfloat16 g_We1eP[256 * 64];       // We1 edge rows (K=32)
__device__ __align__(16) __nv_bfloat16 g_We2P [8 * 128 * 64];
__device__ __align__(16) __nv_bfloat16 g_Wn1P [8 * 256 * 64];
__device__ __align__(16) __nv_bfloat16 g_Wn2P [8 * 128 * 64];

__device__ __forceinline__ float swish_fast(float x) {
    float e = __expf(-x);
    return x * __fdividef(1.f, 1.f + e);
}

// ---------------- common asm helpers -----------------------------------------
__device__ __forceinline__ void mma_bf16(float (&c)[4],
                                         unsigned a0, unsigned a1, unsigned a2, unsigned a3,
                                         unsigned b0, unsigned b1) {
    asm volatile(
        "mma.sync.aligned.m16n8k16.row.col.f32.bf16.bf16.f32 "
        "{%0,%1,%2,%3}, {%4,%5,%6,%7}, {%8,%9}, {%0,%1,%2,%3};"
        : "+f"(c[0]), "+f"(c[1]), "+f"(c[2]), "+f"(c[3])
        : "r"(a0), "r"(a1), "r"(a2), "r"(a3), "r"(b0), "r"(b1));
}

__device__ __forceinline__ void ldsm4(unsigned& r0, unsigned& r1, unsigned& r2, unsigned& r3,
                                      unsigned addr) {
    asm volatile("ldmatrix.sync.aligned.m8n8.x4.shared.b16 {%0,%1,%2,%3}, [%4];"
                 : "=r"(r0), "=r"(r1), "=r"(r2), "=r"(r3) : "r"(addr));
}

#define CP16(dst, src) asm volatile("cp.async.cg.shared.global [%0], [%1], 16;" :: "r"(dst), "l"(src))
#define CPCOMMIT()     asm volatile("cp.async.commit_group;" ::: "memory")
#define CPWAIT1()      asm volatile("cp.async.wait_group 1;" ::: "memory")
#define CPWAIT0()      asm volatile("cp.async.wait_group 0;" ::: "memory")

// split 32 fp32 -> 32 hi + 32 lo bf16, store 128B at dst (16B aligned)
__device__ __forceinline__ void split_store32(const float* x, __nv_bfloat16* dst) {
    unsigned hw[16], lw[16];
    #pragma unroll
    for (int t = 0; t < 16; ++t) {
        __nv_bfloat162 h = __floats2bfloat162_rn(x[2*t], x[2*t+1]);
        __nv_bfloat162 l = __floats2bfloat162_rn(x[2*t]   - __bfloat162float(h.x),
                                                 x[2*t+1] - __bfloat162float(h.y));
        hw[t] = *(unsigned*)&h;
        lw[t] = *(unsigned*)&l;
    }
    uint4* dh = (uint4*)dst;
    uint4* dl = (uint4*)(dst + 32);
    #pragma unroll
    for (int t = 0; t < 4; ++t) {
        dh[t] = make_uint4(hw[4*t], hw[4*t+1], hw[4*t+2], hw[4*t+3]);
        dl[t] = make_uint4(lw[4*t], lw[4*t+1], lw[4*t+2], lw[4*t+3]);
    }
}

// ============================================================================
// Packed GEMM: CTA tile 64(M)x128(N), K-chunks of 32, 256 threads (8 warps 2x4)
// stage: Ah[64][40] Al Bh[128][40] Bl; 80B rows (cf-free ldmatrix), 30720B
// ============================================================================
#define GSTAGE 30720
#define GSMEM  (3 * GSTAGE)      // 92160

__device__ __forceinline__ void g_ldstage(
    const __nv_bfloat16* __restrict__ AP0, const __nv_bfloat16* __restrict__ AP1,
    int splitAt, const __nv_bfloat16* __restrict__ BP, int NBW, int n0,
    int m0, int kc, unsigned smst, int tid)
{
    const __nv_bfloat16* AP = (kc < splitAt) ? AP0 : AP1;
    const int kcl = (kc < splitAt) ? kc : kc - splitAt;
    {
        const int r = tid >> 2, seg = (tid & 3) * 16;
        const char* srcA = (const char*)(AP + ((size_t)kcl * N_PAD + (m0 + r)) * 64);
        CP16(smst + r * 80 + seg,        srcA + seg);
        CP16(smst + 5120 + r * 80 + seg, srcA + 64 + seg);
    }
    {
        const int n = tid >> 1, s0 = (tid & 1) * 32;
        const char* srcB = (const char*)(BP + ((size_t)kc * NBW + n0 + n) * 64);
        CP16(smst + 10240 + n * 80 + s0,      srcB + s0);
        CP16(smst + 10240 + n * 80 + s0 + 16, srcB + s0 + 16);
        CP16(smst + 20480 + n * 80 + s0,      srcB + 64 + s0);
        CP16(smst + 20480 + n * 80 + s0 + 16, srcB + 64 + s0 + 16);
    }
}

__device__ __forceinline__ void g_mma(unsigned st, float (&C)[2][4][4],
                                      int wm, int wn, int lane)
{
    const unsigned aH = st, aL = st + 5120, bH = st + 10240, bL = st + 20480;
    const unsigned aoff = (unsigned)((wm * 32 + (lane & 15)) * 80 + (lane >> 4) * 16);
    const unsigned boff = (unsigned)((wn * 32 + ((lane >> 4) & 1) * 8 + (lane & 7)) * 80
                                     + ((lane >> 3) & 1) * 16);
    #pragma unroll
    for (int ks = 0; ks < 2; ++ks) {
        const unsigned kb = ks * 32;
        unsigned ah[2][4], al[2][4];
        #pragma unroll
        for (int mf = 0; mf < 2; ++mf) {
            ldsm4(ah[mf][0], ah[mf][1], ah[mf][2], ah[mf][3], aH + aoff + mf * 16 * 80 + kb);
            ldsm4(al[mf][0], al[mf][1], al[mf][2], al[mf][3], aL + aoff + mf * 16 * 80 + kb);
        }
        #pragma unroll
        for (int p = 0; p < 2; ++p) {
            unsigned bh[4], bl[4];
            ldsm4(bh[0], bh[1], bh[2], bh[3], bH + boff + p * 16 * 80 + kb);
            ldsm4(bl[0], bl[1], bl[2], bl[3], bL + boff + p * 16 * 80 + kb);
            #pragma unroll
            for (int sub = 0; sub < 2; ++sub) {
                int nf = p * 2 + sub;
                unsigned b0h = bh[sub * 2], b1h = bh[sub * 2 + 1];
                unsigned b0l = bl[sub * 2], b1l = bl[sub * 2 + 1];
                #pragma unroll
                for (int mf = 0; mf < 2; ++mf) {
                    mma_bf16(C[mf][nf], ah[mf][0], ah[mf][1], ah[mf][2], ah[mf][3], b0h, b1h);
                    mma_bf16(C[mf][nf], ah[mf][0], ah[mf][1], ah[mf][2], ah[mf][3], b0l, b1l);
                    mma_bf16(C[mf][nf], al[mf][0], al[mf][1], al[mf][2], al[mf][3], b0h, b1h);
                }
            }
        }
    }
}

__device__ __forceinline__ void gemm_run(
    const __nv_bfloat16* __restrict__ AP0, const __nv_bfloat16* __restrict__ AP1,
    int splitAt, const __nv_bfloat16* __restrict__ BP, int NBW, int n0,
    int m0, int KT, unsigned smb, float (&C)[2][4][4],
    int tid, int wm, int wn, int lane)
{
    g_ldstage(AP0, AP1, splitAt, BP, NBW, n0, m0, 0, smb, tid);          CPCOMMIT();
    g_ldstage(AP0, AP1, splitAt, BP, NBW, n0, m0, 1, smb + GSTAGE, tid); CPCOMMIT();
    for (int kc = 0; kc < KT; ++kc) {
        if (kc < KT - 1) CPWAIT1(); else CPWAIT0();
        __syncthreads();
        if (kc + 2 < KT) {
            g_ldstage(AP0, AP1, splitAt, BP, NBW, n0, m0, kc + 2,
                      smb + (unsigned)((kc + 2) % 3) * GSTAGE, tid);
            CPCOMMIT();
        }
        g_mma(smb + (unsigned)(kc % 3) * GSTAGE, C, wm, wn, lane);
    }
}

__device__ __forceinline__ void stage_C(float (&C)[2][4][4], float* lnbuf,
                                        int wm, int wn, int lane)
{
    const int gr = lane >> 2, tc = lane & 3;
    #pragma unroll
    for (int mf = 0; mf < 2; ++mf) {
        int lr = wm * 32 + mf * 16 + gr;
        #pragma unroll
        for (int nf = 0; nf < 4; ++nf) {
            int col = wn * 32 + nf * 8 + 2 * tc;
            *(float2*)&lnbuf[lr * 132 + col]       = make_float2(C[mf][nf][0], C[mf][nf][1]);
            *(float2*)&lnbuf[(lr + 8) * 132 + col] = make_float2(C[mf][nf][2], C[mf][nf][3]);
        }
    }
}

#define GEMM_HEAD()                                                            \
    extern __shared__ __align__(16) char sm[];                                 \
    const unsigned smb = (unsigned)__cvta_generic_to_shared(sm);               \
    const int tid = threadIdx.x;                                               \
    const int w = tid >> 5, lane = tid & 31;                                   \
    const int wm = w & 1, wn = w >> 1;                                         \
    const int m0 = blockIdx.x * 64;                                            \
    float C[2][4][4];                                                          \
    _Pragma("unroll") for (int mf = 0; mf < 2; ++mf)                           \
        _Pragma("unroll") for (int nf = 0; nf < 4; ++nf)                       \
            _Pragma("unroll") for (int i = 0; i < 4; ++i) C[mf][nf][i] = 0.f;

// ---------------------------------------------------------------------------
// KW: pack all weights to bf16 hi/lo tile layout.  6400 threads.
// ---------------------------------------------------------------------------
__global__ void kw_pack(const float* __restrict__ We1, const float* __restrict__ We2,
                        const float* __restrict__ Wn1, const float* __restrict__ Wn2)
{
    int idx = blockIdx.x * 256 + threadIdx.x;
    float v[32];
    __nv_bfloat16* dst;
    if (idx < 2048) {                               // BP1: [4][512]
        int kc = idx >> 9, n = idx & 511;
        int rb = (n < 256) ? kc * 32 : 128 + kc * 32;
        int c = n & 255;
        #pragma unroll
        for (int k = 0; k < 32; ++k) v[k] = We1[(rb + k) * 256 + c];
        dst = g_BP1 + (size_t)idx * 64;
    } else if (idx < 2304) {                        // We1eP: [256]
        int n = idx - 2048;
        #pragma unroll
        for (int k = 0; k < 32; ++k) v[k] = We1[(256 + k) * 256 + n];
        dst = g_We1eP + (size_t)n * 64;
    } else if (idx < 3328) {                        // We2P: [8][128]
        int t = idx - 2304, kc = t >> 7, n = t & 127;
        #pragma unroll
        for (int k = 0; k < 32; ++k) v[k] = We2[(kc * 32 + k) * 128 + n];
        dst = g_We2P + (size_t)t * 64;
    } else if (idx < 5376) {                        // Wn1P: [8][256]
        int t = idx - 3328, kc = t >> 8, n = t & 255;
        #pragma unroll
        for (int k = 0; k < 32; ++k) v[k] = Wn1[(kc * 32 + k) * 256 + n];
        dst = g_Wn1P + (size_t)t * 64;
    } else if (idx < 6400) {                        // Wn2P: [8][128]
        int t = idx - 5376, kc = t >> 7, n = t & 127;
        #pragma unroll
        for (int k = 0; k < 32; ++k) v[k] = Wn2[(kc * 32 + k) * 128 + n];
        dst = g_Wn2P + (size_t)t * 64;
    } else return;
    split_store32(v, dst);
}

// ---------------------------------------------------------------------------
// K0: pack node -> g_nodeP.  grid 782 x 256
// ---------------------------------------------------------------------------
__global__ __launch_bounds__(256) void k0_pack(const float* __restrict__ node)
{
    int r = blockIdx.x * 64 + (threadIdx.x >> 2);
    int part = threadIdx.x & 3;
    if (r >= N_NODES) return;
    const float* src = node + (size_t)r * DIM + part * 32;
    float v[32];
    #pragma unroll
    for (int q = 0; q < 8; ++q) *(float4*)&v[4 * q] = ((const float4*)src)[q];
    split_store32(v, g_nodeP + ((size_t)part * N_PAD + r) * 64);
}

// ---------------------------------------------------------------------------
// K1: S = node@We1[0:128,:], R = node@We1[128:256,:] + be1.  grid (782, 4)
// ---------------------------------------------------------------------------
__global__ __launch_bounds__(256, 2) void k1_g(const float* __restrict__ be1)
{
    GEMM_HEAD();
    const int n0g = blockIdx.y * 128;
    gemm_run(g_nodeP, g_nodeP, 4, g_BP1, 512, n0g, m0, 4, smb, C, tid, wm, wn, lane);

    const int gr = lane >> 2, tc = lane & 3;
    #pragma unroll
    for (int mf = 0; mf < 2; ++mf) {
        int row = m0 + wm * 32 + mf * 16 + gr;
        #pragma unroll
        for (int nf = 0; nf < 4; ++nf) {
            int gcol = n0g + wn * 32 + nf * 8 + 2 * tc;
            int which = gcol >> 8;
            int col = gcol & 255;
            float b0 = which ? be1[col] : 0.f;
            float b1 = which ? be1[col + 1] : 0.f;
            float* outp = which ? g_R : g_S;
            if (row < N_NODES)
                *(float2*)(outp + (size_t)row * HID + col) =
                    make_float2(C[mf][nf][0] + b0, C[mf][nf][1] + b1);
            if (row + 8 < N_NODES)
                *(float2*)(outp + (size_t)(row + 8) * HID + col) =
                    make_float2(C[mf][nf][2] + b0, C[mf][nf][3] + b1);
        }
    }
}

// ---------------------------------------------------------------------------
// K3: aggln = LN(Hagg @ We2 / 16 + be2) * mask -> packed agglnP.  grid (782)
// ---------------------------------------------------------------------------
__global__ __launch_bounds__(256, 2) void k3_g(
    const float* __restrict__ be2, const float* __restrict__ gmsg,
    const float* __restrict__ bmsg, const float* __restrict__ mask)
{
    GEMM_HEAD();
    gemm_run(g_HaggP, g_HaggP, 8, g_We2P, 128, 0, m0, 8, smb, C, tid, wm, wn, lane);
    __syncthreads();
    float* lnbuf = (float*)sm;
    stage_C(C, lnbuf, wm, wn, lane);
    __syncthreads();

    const int r = tid >> 2, part = tid & 3;
    const int grow = m0 + r;
    float x[32], s = 0.f, ss = 0.f;
    #pragma unroll
    for (int j = 0; j < 32; ++j) {
        int col = part * 32 + j;
        float t = lnbuf[r * 132 + col] * (1.f / DEG) + be2[col];
        x[j] = t; s += t; ss += t * t;
    }
    s  += __shfl_xor_sync(~0u, s, 1);  s  += __shfl_xor_sync(~0u, s, 2);
    ss += __shfl_xor_sync(~0u, ss, 1); ss += __shfl_xor_sync(~0u, ss, 2);
    float mean = s * (1.f / 128.f);
    float var  = ss * (1.f / 128.f) - mean * mean;
    float inv  = rsqrtf(var + EPS);
    if (grow < N_NODES) {
        float mk = mask[grow];
        float y[32];
        #pragma unroll
        for (int j = 0; j < 32; ++j) {
            int col = part * 32 + j;
            y[j] = ((x[j] - mean) * inv * gmsg[col] + bmsg[col]) * mk;
        }
        split_store32(y, g_agglnP + ((size_t)part * N_PAD + grow) * 64);
    }
}

// ---------------------------------------------------------------------------
// K4a: H = swish([node | aggln] @ Wn1 + bn1) -> packed HP.  grid (782, 2)
// ---------------------------------------------------------------------------
__global__ __launch_bounds__(256, 2) void k4a_g(const float* __restrict__ bn1)
{
    GEMM_HEAD();
    const int n0g = blockIdx.y * 128;
    gemm_run(g_nodeP, g_agglnP, 4, g_Wn1P, 256, n0g, m0, 8, smb, C, tid, wm, wn, lane);
    __syncthreads();
    float* lnbuf = (float*)sm;
    stage_C(C, lnbuf, wm, wn, lane);
    __syncthreads();

    const int r = tid >> 2, part = tid & 3;
    const int grow = m0 + r;
    if (grow < N_NODES) {
        float y[32];
        #pragma unroll
        for (int j = 0; j < 32; ++j) {
            int col = part * 32 + j;
            y[j] = swish_fast(lnbuf[r * 132 + col] + bn1[n0g + col]);
        }
        split_store32(y, g_HP + ((size_t)((n0g >> 5) + part) * N_PAD + grow) * 64);
    }
}

// ---------------------------------------------------------------------------
// K4b: out = LN(H @ Wn2 + bn2 + node) * mask.  grid (782)
// ---------------------------------------------------------------------------
__global__ __launch_bounds__(256, 2) void k4b_g(
    const float* __restrict__ node, const float* __restrict__ bn2,
    const float* __restrict__ gnode, const float* __restrict__ bnode,
    const float* __restrict__ mask, float* __restrict__ out)
{
    GEMM_HEAD();
    gemm_run(g_HP, g_HP, 8, g_Wn2P, 128, 0, m0, 8, smb, C, tid, wm, wn, lane);
    __syncthreads();
    float* lnbuf = (float*)sm;
    stage_C(C, lnbuf, wm, wn, lane);
    __syncthreads();

    const int r = tid >> 2, part = tid & 3;
    const int grow = m0 + r;
    float x[32], s = 0.f, ss = 0.f;
    #pragma unroll
    for (int j = 0; j < 32; ++j) {
        int col = part * 32 + j;
        float res = (grow < N_NODES) ? node[(size_t)grow * DIM + col] : 0.f;
        float t = lnbuf[r * 132 + col] + bn2[col] + res;
        x[j] = t; s += t; ss += t * t;
    }
    s  += __shfl_xor_sync(~0u, s, 1);  s  += __shfl_xor_sync(~0u, s, 2);
    ss += __shfl_xor_sync(~0u, ss, 1); ss += __shfl_xor_sync(~0u, ss, 2);
    float mean = s * (1.f / 128.f);
    float var  = ss * (1.f / 128.f) - mean * mean;
    float inv  = rsqrtf(var + EPS);
    if (grow < N_NODES) {
        float mk = mask[grow];
        float* op = out + (size_t)grow * DIM + part * 32;
        #pragma unroll
        for (int q = 0; q < 8; ++q) {
            float4 o;
            int j = 4 * q, col = part * 32 + j;
            o.x = ((x[j]     - mean) * inv * gnode[col]     + bnode[col])     * mk;
            o.y = ((x[j + 1] - mean) * inv * gnode[col + 1] + bnode[col + 1]) * mk;
            o.z = ((x[j + 2] - mean) * inv * gnode[col + 2] + bnode[col + 2]) * mk;
            o.w = ((x[j + 3] - mean) * inv * gnode[col + 3] + bnode[col + 3]) * mk;
            *(float4*)(op + j) = o;
        }
    }
}

// ============================================================================
// K2F: edge projection + gather + swish + per-node reduce -> packed HaggP
// CTA 128 edges (8 nodes) x 128 cols, 512 threads.  grid (6250, 2)
// ============================================================================
#define KPAD 40
#define TILE_HALVES (128 * KPAD)
#define STAGE_BYTES (4 * 128 * KPAD * 2)

__device__ __forceinline__ void sts_split4(__nv_bfloat16* Hp, __nv_bfloat16* Lp, int off,
                                           float x0, float x1, float x2, float x3) {
    __nv_bfloat162 h01 = __floats2bfloat162_rn(x0, x1);
    __nv_bfloat162 h23 = __floats2bfloat162_rn(x2, x3);
    __nv_bfloat162 l01 = __floats2bfloat162_rn(x0 - __bfloat162float(h01.x),
                                               x1 - __bfloat162float(h01.y));
    __nv_bfloat162 l23 = __floats2bfloat162_rn(x2 - __bfloat162float(h23.x),
                                               x3 - __bfloat162float(h23.y));
    *(uint2*)(Hp + off) = make_uint2(*(unsigned*)&h01, *(unsigned*)&h23);
    *(uint2*)(Lp + off) = make_uint2(*(unsigned*)&l01, *(unsigned*)&l23);
}

__device__ __forceinline__ void mma_chunk_p(
    const __nv_bfloat16* Ah, const __nv_bfloat16* Al,
    const __nv_bfloat16* Bh, const __nv_bfloat16* Bl,
    float (&C)[2][4][4], int wm, int wn, int lane)
{
    unsigned aH = (unsigned)__cvta_generic_to_shared(Ah);
    unsigned aL = (unsigned)__cvta_generic_to_shared(Al);
    unsigned bH = (unsigned)__cvta_generic_to_shared(Bh);
    unsigned bL = (unsigned)__cvta_generic_to_shared(Bl);
    const unsigned aoff = (unsigned)((wm * 32 + (lane & 15)) * 80 + (lane >> 4) * 16);
    const unsigned boff = (unsigned)((wn * 32 + ((lane >> 4) & 1) * 8 + (lane & 7)) * 80
                                     + ((lane >> 3) & 1) * 16);
    #pragma unroll
    for (int ks = 0; ks < 2; ++ks) {
        const unsigned kb = ks * 32;
        unsigned ah[2][4], al[2][4];
        #pragma unroll
        for (int mf = 0; mf < 2; ++mf) {
            ldsm4(ah[mf][0], ah[mf][1], ah[mf][2], ah[mf][3], aH + aoff + mf * 16 * 80 + kb);
            ldsm4(al[mf][0], al[mf][1], al[mf][2], al[mf][3], aL + aoff + mf * 16 * 80 + kb);
        }
        #pragma unroll
        for (int p = 0; p < 2; ++p) {
            unsigned bh[4], bl[4];
            ldsm4(bh[0], bh[1], bh[2], bh[3], bH + boff + p * 16 * 80 + kb);
            ldsm4(bl[0], bl[1], bl[2], bl[3], bL + boff + p * 16 * 80 + kb);
            #pragma unroll
            for (int sub = 0; sub < 2; ++sub) {
                int nf = p * 2 + sub;
                unsigned b0h = bh[sub * 2], b1h = bh[sub * 2 + 1];
                unsigned b0l = bl[sub * 2], b1l = bl[sub * 2 + 1];
                #pragma unroll
                for (int mf = 0; mf < 2; ++mf) {
                    mma_bf16(C[mf][nf], ah[mf][0], ah[mf][1], ah[mf][2], ah[mf][3], b0h, b1h);
                    mma_bf16(C[mf][nf], ah[mf][0], ah[mf][1], ah[mf][2], ah[mf][3], b0l, b1l);
                    mma_bf16(C[mf][nf], al[mf][0], al[mf][1], al[mf][2], al[mf][3], b0h, b1h);
                }
            }
        }
    }
}

__global__ __launch_bounds__(512, 1) void k2f(
    const float* __restrict__ edge_feat, const int* __restrict__ senders)
{
    __shared__ __align__(16) unsigned char smstage[STAGE_BYTES];
    __shared__ int   ss[128];
    __shared__ float Rs[8][128];

    __nv_bfloat16* Ah = (__nv_bfloat16*)smstage;
    __nv_bfloat16* Al = Ah + TILE_HALVES;
    __nv_bfloat16* Bh = Al + TILE_HALVES;
    __nv_bfloat16* Bl = Bh + TILE_HALVES;

    const int tid = threadIdx.x;
    const int w = tid >> 5, lane = tid & 31;
    const int wm = w & 3, wn = w >> 2;
    const int gr = lane >> 2, tc = lane & 3;

    const int e0 = blockIdx.x * 128;
    const int n0 = blockIdx.y * 128;
    const int node0 = e0 >> 4;

    // B: cp.async prepacked We1eP (hi/lo, 80B-stride dst)
    {
        const unsigned bh = (unsigned)__cvta_generic_to_shared(Bh);
        const unsigned bl = (unsigned)__cvta_generic_to_shared(Bl);
        const int n = tid >> 2, sg = (tid & 3) * 16;
        const char* srcB = (const char*)(g_We1eP + (size_t)(n0 + n) * 64);
        CP16(bh + n * 80 + sg, srcB + sg);
        CP16(bl + n * 80 + sg, srcB + 64 + sg);
        CPCOMMIT();
    }
    // A: load edge_feat, split into smem
    {
        #pragma unroll
        for (int q = 0; q < 2; ++q) {
            int idx = tid + q * 512;
            int r = idx >> 3, c4 = (idx & 7) * 4;
            float4 v = *(const float4*)(edge_feat + (size_t)(e0 + r) * EDIM + c4);
            sts_split4(Ah, Al, r * KPAD + c4, v.x, v.y, v.z, v.w);
        }
    }
    if (tid < 128) ss[tid] = senders[e0 + tid];
    #pragma unroll
    for (int q = 0; q < 2; ++q) {
        int idx = tid + q * 512;
        int r = idx >> 7, c = idx & 127;
        Rs[r][c] = g_R[(size_t)(node0 + r) * HID + n0 + c];
    }
    CPWAIT0();
    __syncthreads();

    float C[2][4][4];
    #pragma unroll
    for (int mf = 0; mf < 2; ++mf)
        #pragma unroll
        for (int nf = 0; nf < 4; ++nf)
            #pragma unroll
            for (int i = 0; i < 4; ++i) C[mf][nf][i] = 0.f;

    mma_chunk_p(Ah, Al, Bh, Bl, C, wm, wn, lane);

    #pragma unroll
    for (int mf = 0; mf < 2; ++mf) {
        const int lrow = wm * 32 + mf * 16;
        const int nloc = lrow >> 4;
        const int snd0 = ss[lrow + gr];
        const int snd1 = ss[lrow + gr + 8];
        const float* s0p = g_S + (size_t)snd0 * HID + n0;
        const float* s1p = g_S + (size_t)snd1 * HID + n0;
        #pragma unroll
        for (int nf = 0; nf < 4; ++nf) {
            const int colL = wn * 32 + nf * 8 + 2 * tc;
            float2 s0 = *(const float2*)(s0p + colL);
            float2 s1 = *(const float2*)(s1p + colL);
            float r0 = Rs[nloc][colL], r1 = Rs[nloc][colL + 1];
            float h0 = swish_fast(C[mf][nf][0] + s0.x + r0)
                     + swish_fast(C[mf][nf][2] + s1.x + r0);
            float h1 = swish_fast(C[mf][nf][1] + s0.y + r1)
                     + swish_fast(C[mf][nf][3] + s1.y + r1);
            #pragma unroll
            for (int o = 4; o <= 16; o <<= 1) {
                h0 += __shfl_xor_sync(0xffffffffu, h0, o);
                h1 += __shfl_xor_sync(0xffffffffu, h1, o);
            }
            if (gr == 0) {
                int gcol = n0 + colL;
                int kc = gcol >> 5, kin = gcol & 31;
                size_t base = ((size_t)kc * N_PAD + node0 + nloc) * 64 + kin;
                __nv_bfloat162 hh = __floats2bfloat162_rn(h0, h1);
                __nv_bfloat162 ll = __floats2bfloat162_rn(h0 - __bfloat162float(hh.x),
                                                          h1 - __bfloat162float(hh.y));
                *(unsigned*)&g_HaggP[base]      = *(unsigned*)&hh;
                *(unsigned*)&g_HaggP[base + 32] = *(unsigned*)&ll;
            }
        }
    }
}

// ---------------------------------------------------------------------------
extern "C" void kernel_launch(void* const* d_in, const int* in_sizes, int n_in,
                              void* d_out, int out_size)
{
    const float* node      = (const float*)d_in[0];
    const float* edge_feat = (const float*)d_in[1];
    const float* mask      = (const float*)d_in[2];
    const float* We1       = (const float*)d_in[3];
    const float* be1       = (const float*)d_in[4];
    const float* We2       = (const float*)d_in[5];
    const float* be2       = (const float*)d_in[6];
    const float* gmsg      = (const float*)d_in[7];
    const float* bmsg      = (const float*)d_in[8];
    const float* Wn1       = (const float*)d_in[9];
    const float* bn1       = (const float*)d_in[10];
    const float* Wn2       = (const float*)d_in[11];
    const float* bn2       = (const float*)d_in[12];
    const float* gnode     = (const float*)d_in[13];
    const float* bnode     = (const float*)d_in[14];
    const int*   senders   = (const int*)d_in[15];
    float* out = (float*)d_out;

    cudaFuncSetAttribute(k1_g,  cudaFuncAttributeMaxDynamicSharedMemorySize, GSMEM);
    cudaFuncSetAttribute(k3_g,  cudaFuncAttributeMaxDynamicSharedMemorySize, GSMEM);
    cudaFuncSetAttribute(k4a_g, cudaFuncAttributeMaxDynamicSharedMemorySize, GSMEM);
    cudaFuncSetAttribute(k4b_g, cudaFuncAttributeMaxDynamicSharedMemorySize, GSMEM);

    const int mb = N_PAD / 64;   // 782

    kw_pack<<<25, 256>>>(We1, We2, Wn1, Wn2);
    k0_pack<<<mb, 256>>>(node);
    k1_g   <<<dim3(mb, 4), 256, GSMEM>>>(be1);
    k2f    <<<dim3(E_EDGES / 128, 2), 512>>>(edge_feat, senders);
    k3_g   <<<mb, 256, GSMEM>>>(be2, gmsg, bmsg, mask);
    k4a_g  <<<dim3(mb, 2), 256, GSMEM>>>(bn1);
    k4b_g  <<<mb, 256, GSMEM>>>(node, bn2, gnode, bnode, mask, out);
}

// round 7
// speedup vs baseline: 1.2276x; 1.2276x over previous
#include <cuda_runtime.h>
#include <cuda_bf16.h>
#include <math.h>

#define N_NODES 50000
#define N_PAD   50048            // 782 * 64
#define E_EDGES 800000
#define DIM     128
#define EDIM    32
#define HID     256
#define DEG     16
#define EPS     1e-5f

// ---------------- scratch (device globals; allocation-free rule) ------------
__device__ float g_S[N_NODES * HID];
__device__ float g_R[N_NODES * HID];
// packed activations: [kc][row][64 halves] = 32 hi || 32 lo  (128B per (kc,row))
__device__ __align__(16) __nv_bfloat16 g_nodeP [4ull * N_PAD * 64];
__device__ __align__(16) __nv_bfloat16 g_HaggP [8ull * N_PAD * 64];
__device__ __align__(16) __nv_bfloat16 g_agglnP[4ull * N_PAD * 64];
__device__ __align__(16) __nv_bfloat16 g_HP    [8ull * N_PAD * 64];
// packed weights: [kc][n][64 halves]
__device__ __align__(16) __nv_bfloat16 g_BP1  [4 * 512 * 64];   // [We1_top | We1_mid]
__device__ __align__(16) __nv_bfloat16 g_We1eP[256 * 64];       // We1 edge rows (K=32)
__device__ __align__(16) __nv_bfloat16 g_We2P [8 * 128 * 64];
__device__ __align__(16) __nv_bfloat16 g_Wn1P [8 * 256 * 64];
__device__ __align__(16) __nv_bfloat16 g_Wn2P [8 * 128 * 64];

__device__ __forceinline__ float swish_fast(float x) {
    float e = __expf(-x);
    return x * __fdividef(1.f, 1.f + e);
}

// ---------------- common asm helpers -----------------------------------------
__device__ __forceinline__ void mma_bf16(float (&c)[4],
                                         unsigned a0, unsigned a1, unsigned a2, unsigned a3,
                                         unsigned b0, unsigned b1) {
    asm volatile(
        "mma.sync.aligned.m16n8k16.row.col.f32.bf16.bf16.f32 "
        "{%0,%1,%2,%3}, {%4,%5,%6,%7}, {%8,%9}, {%0,%1,%2,%3};"
        : "+f"(c[0]), "+f"(c[1]), "+f"(c[2]), "+f"(c[3])
        : "r"(a0), "r"(a1), "r"(a2), "r"(a3), "r"(b0), "r"(b1));
}

__device__ __forceinline__ void ldsm4(unsigned& r0, unsigned& r1, unsigned& r2, unsigned& r3,
                                      unsigned addr) {
    asm volatile("ldmatrix.sync.aligned.m8n8.x4.shared.b16 {%0,%1,%2,%3}, [%4];"
                 : "=r"(r0), "=r"(r1), "=r"(r2), "=r"(r3) : "r"(addr));
}

#define CP16(dst, src) asm volatile("cp.async.cg.shared.global [%0], [%1], 16;" :: "r"(dst), "l"(src))
#define CPCOMMIT()     asm volatile("cp.async.commit_group;" ::: "memory")
#define CPWAIT1()      asm volatile("cp.async.wait_group 1;" ::: "memory")
#define CPWAIT0()      asm volatile("cp.async.wait_group 0;" ::: "memory")

// split 32 fp32 -> 32 hi + 32 lo bf16, store 128B at dst (16B aligned)
__device__ __forceinline__ void split_store32(const float* x, __nv_bfloat16* dst) {
    unsigned hw[16], lw[16];
    #pragma unroll
    for (int t = 0; t < 16; ++t) {
        __nv_bfloat162 h = __floats2bfloat162_rn(x[2*t], x[2*t+1]);
        __nv_bfloat162 l = __floats2bfloat162_rn(x[2*t]   - __bfloat162float(h.x),
                                                 x[2*t+1] - __bfloat162float(h.y));
        hw[t] = *(unsigned*)&h;
        lw[t] = *(unsigned*)&l;
    }
    uint4* dh = (uint4*)dst;
    uint4* dl = (uint4*)(dst + 32);
    #pragma unroll
    for (int t = 0; t < 4; ++t) {
        dh[t] = make_uint4(hw[4*t], hw[4*t+1], hw[4*t+2], hw[4*t+3]);
        dl[t] = make_uint4(lw[4*t], lw[4*t+1], lw[4*t+2], lw[4*t+3]);
    }
}

__device__ __forceinline__ void sts_split4(__nv_bfloat16* Hp, __nv_bfloat16* Lp, int off,
                                           float x0, float x1, float x2, float x3) {
    __nv_bfloat162 h01 = __floats2bfloat162_rn(x0, x1);
    __nv_bfloat162 h23 = __floats2bfloat162_rn(x2, x3);
    __nv_bfloat162 l01 = __floats2bfloat162_rn(x0 - __bfloat162float(h01.x),
                                               x1 - __bfloat162float(h01.y));
    __nv_bfloat162 l23 = __floats2bfloat162_rn(x2 - __bfloat162float(h23.x),
                                               x3 - __bfloat162float(h23.y));
    *(uint2*)(Hp + off) = make_uint2(*(unsigned*)&h01, *(unsigned*)&h23);
    *(uint2*)(Lp + off) = make_uint2(*(unsigned*)&l01, *(unsigned*)&l23);
}

// ============================================================================
// Packed GEMM: CTA tile 64(M)x128(N), K-chunks of 32, 256 threads (8 warps 2x4)
// stage: Ah[64][40] Al Bh[128][40] Bl; 80B rows (cf-free ldmatrix), 30720B
// ============================================================================
#define GSTAGE 30720
#define GSMEM  (3 * GSTAGE)      // 92160

__device__ __forceinline__ void g_ldstage(
    const __nv_bfloat16* __restrict__ AP0, const __nv_bfloat16* __restrict__ AP1,
    int splitAt, const __nv_bfloat16* __restrict__ BP, int NBW, int n0,
    int m0, int kc, unsigned smst, int tid)
{
    const __nv_bfloat16* AP = (kc < splitAt) ? AP0 : AP1;
    const int kcl = (kc < splitAt) ? kc : kc - splitAt;
    {
        const int r = tid >> 2, seg = (tid & 3) * 16;
        const char* srcA = (const char*)(AP + ((size_t)kcl * N_PAD + (m0 + r)) * 64);
        CP16(smst + r * 80 + seg,        srcA + seg);
        CP16(smst + 5120 + r * 80 + seg, srcA + 64 + seg);
    }
    {
        const int n = tid >> 1, s0 = (tid & 1) * 32;
        const char* srcB = (const char*)(BP + ((size_t)kc * NBW + n0 + n) * 64);
        CP16(smst + 10240 + n * 80 + s0,      srcB + s0);
        CP16(smst + 10240 + n * 80 + s0 + 16, srcB + s0 + 16);
        CP16(smst + 20480 + n * 80 + s0,      srcB + 64 + s0);
        CP16(smst + 20480 + n * 80 + s0 + 16, srcB + 64 + s0 + 16);
    }
}

__device__ __forceinline__ void g_mma(unsigned st, float (&C)[2][4][4],
                                      int wm, int wn, int lane)
{
    const unsigned aH = st, aL = st + 5120, bH = st + 10240, bL = st + 20480;
    const unsigned aoff = (unsigned)((wm * 32 + (lane & 15)) * 80 + (lane >> 4) * 16);
    const unsigned boff = (unsigned)((wn * 32 + ((lane >> 4) & 1) * 8 + (lane & 7)) * 80
                                     + ((lane >> 3) & 1) * 16);
    #pragma unroll
    for (int ks = 0; ks < 2; ++ks) {
        const unsigned kb = ks * 32;
        unsigned ah[2][4], al[2][4];
        #pragma unroll
        for (int mf = 0; mf < 2; ++mf) {
            ldsm4(ah[mf][0], ah[mf][1], ah[mf][2], ah[mf][3], aH + aoff + mf * 16 * 80 + kb);
            ldsm4(al[mf][0], al[mf][1], al[mf][2], al[mf][3], aL + aoff + mf * 16 * 80 + kb);
        }
        #pragma unroll
        for (int p = 0; p < 2; ++p) {
            unsigned bh[4], bl[4];
            ldsm4(bh[0], bh[1], bh[2], bh[3], bH + boff + p * 16 * 80 + kb);
            ldsm4(bl[0], bl[1], bl[2], bl[3], bL + boff + p * 16 * 80 + kb);
            #pragma unroll
            for (int sub = 0; sub < 2; ++sub) {
                int nf = p * 2 + sub;
                unsigned b0h = bh[sub * 2], b1h = bh[sub * 2 + 1];
                unsigned b0l = bl[sub * 2], b1l = bl[sub * 2 + 1];
                #pragma unroll
                for (int mf = 0; mf < 2; ++mf) {
                    mma_bf16(C[mf][nf], ah[mf][0], ah[mf][1], ah[mf][2], ah[mf][3], b0h, b1h);
                    mma_bf16(C[mf][nf], ah[mf][0], ah[mf][1], ah[mf][2], ah[mf][3], b0l, b1l);
                    mma_bf16(C[mf][nf], al[mf][0], al[mf][1], al[mf][2], al[mf][3], b0h, b1h);
                }
            }
        }
    }
}

__device__ __forceinline__ void gemm_run(
    const __nv_bfloat16* __restrict__ AP0, const __nv_bfloat16* __restrict__ AP1,
    int splitAt, const __nv_bfloat16* __restrict__ BP, int NBW, int n0,
    int m0, int KT, unsigned smb, float (&C)[2][4][4],
    int tid, int wm, int wn, int lane)
{
    g_ldstage(AP0, AP1, splitAt, BP, NBW, n0, m0, 0, smb, tid);          CPCOMMIT();
    g_ldstage(AP0, AP1, splitAt, BP, NBW, n0, m0, 1, smb + GSTAGE, tid); CPCOMMIT();
    for (int kc = 0; kc < KT; ++kc) {
        if (kc < KT - 1) CPWAIT1(); else CPWAIT0();
        __syncthreads();
        if (kc + 2 < KT) {
            g_ldstage(AP0, AP1, splitAt, BP, NBW, n0, m0, kc + 2,
                      smb + (unsigned)((kc + 2) % 3) * GSTAGE, tid);
            CPCOMMIT();
        }
        g_mma(smb + (unsigned)(kc % 3) * GSTAGE, C, wm, wn, lane);
    }
}

__device__ __forceinline__ void stage_C(float (&C)[2][4][4], float* lnbuf,
                                        int wm, int wn, int lane)
{
    const int gr = lane >> 2, tc = lane & 3;
    #pragma unroll
    for (int mf = 0; mf < 2; ++mf) {
        int lr = wm * 32 + mf * 16 + gr;
        #pragma unroll
        for (int nf = 0; nf < 4; ++nf) {
            int col = wn * 32 + nf * 8 + 2 * tc;
            *(float2*)&lnbuf[lr * 132 + col]       = make_float2(C[mf][nf][0], C[mf][nf][1]);
            *(float2*)&lnbuf[(lr + 8) * 132 + col] = make_float2(C[mf][nf][2], C[mf][nf][3]);
        }
    }
}

#define GEMM_HEAD()                                                            \
    extern __shared__ __align__(16) char sm[];                                 \
    const unsigned smb = (unsigned)__cvta_generic_to_shared(sm);               \
    const int tid = threadIdx.x;                                               \
    const int w = tid >> 5, lane = tid & 31;                                   \
    const int wm = w & 1, wn = w >> 1;                                         \
    const int m0 = blockIdx.x * 64;                                            \
    float C[2][4][4];                                                          \
    _Pragma("unroll") for (int mf = 0; mf < 2; ++mf)                           \
        _Pragma("unroll") for (int nf = 0; nf < 4; ++nf)                       \
            _Pragma("unroll") for (int i = 0; i < 4; ++i) C[mf][nf][i] = 0.f;

// ---------------------------------------------------------------------------
// KW: pack all weights to bf16 hi/lo tile layout.  6400 threads.
// ---------------------------------------------------------------------------
__global__ void kw_pack(const float* __restrict__ We1, const float* __restrict__ We2,
                        const float* __restrict__ Wn1, const float* __restrict__ Wn2)
{
    int idx = blockIdx.x * 256 + threadIdx.x;
    float v[32];
    __nv_bfloat16* dst;
    if (idx < 2048) {                               // BP1: [4][512]
        int kc = idx >> 9, n = idx & 511;
        int rb = (n < 256) ? kc * 32 : 128 + kc * 32;
        int c = n & 255;
        #pragma unroll
        for (int k = 0; k < 32; ++k) v[k] = We1[(rb + k) * 256 + c];
        dst = g_BP1 + (size_t)idx * 64;
    } else if (idx < 2304) {                        // We1eP: [256]
        int n = idx - 2048;
        #pragma unroll
        for (int k = 0; k < 32; ++k) v[k] = We1[(256 + k) * 256 + n];
        dst = g_We1eP + (size_t)n * 64;
    } else if (idx < 3328) {                        // We2P: [8][128]
        int t = idx - 2304, kc = t >> 7, n = t & 127;
        #pragma unroll
        for (int k = 0; k < 32; ++k) v[k] = We2[(kc * 32 + k) * 128 + n];
        dst = g_We2P + (size_t)t * 64;
    } else if (idx < 5376) {                        // Wn1P: [8][256]
        int t = idx - 3328, kc = t >> 8, n = t & 255;
        #pragma unroll
        for (int k = 0; k < 32; ++k) v[k] = Wn1[(kc * 32 + k) * 256 + n];
        dst = g_Wn1P + (size_t)t * 64;
    } else if (idx < 6400) {                        // Wn2P: [8][128]
        int t = idx - 5376, kc = t >> 7, n = t & 127;
        #pragma unroll
        for (int k = 0; k < 32; ++k) v[k] = Wn2[(kc * 32 + k) * 128 + n];
        dst = g_Wn2P + (size_t)t * 64;
    } else return;
    split_store32(v, dst);
}

// ---------------------------------------------------------------------------
// K0: pack node -> g_nodeP.  grid 782 x 256
// ---------------------------------------------------------------------------
__global__ __launch_bounds__(256) void k0_pack(const float* __restrict__ node)
{
    int r = blockIdx.x * 64 + (threadIdx.x >> 2);
    int part = threadIdx.x & 3;
    if (r >= N_NODES) return;
    const float* src = node + (size_t)r * DIM + part * 32;
    float v[32];
    #pragma unroll
    for (int q = 0; q < 8; ++q) *(float4*)&v[4 * q] = ((const float4*)src)[q];
    split_store32(v, g_nodeP + ((size_t)part * N_PAD + r) * 64);
}

// ---------------------------------------------------------------------------
// K1: S = node@We1[0:128,:], R = node@We1[128:256,:] + be1.  grid (782, 4)
// ---------------------------------------------------------------------------
__global__ __launch_bounds__(256, 2) void k1_g(const float* __restrict__ be1)
{
    GEMM_HEAD();
    const int n0g = blockIdx.y * 128;
    gemm_run(g_nodeP, g_nodeP, 4, g_BP1, 512, n0g, m0, 4, smb, C, tid, wm, wn, lane);

    const int gr = lane >> 2, tc = lane & 3;
    #pragma unroll
    for (int mf = 0; mf < 2; ++mf) {
        int row = m0 + wm * 32 + mf * 16 + gr;
        #pragma unroll
        for (int nf = 0; nf < 4; ++nf) {
            int gcol = n0g + wn * 32 + nf * 8 + 2 * tc;
            int which = gcol >> 8;
            int col = gcol & 255;
            float b0 = which ? be1[col] : 0.f;
            float b1 = which ? be1[col + 1] : 0.f;
            float* outp = which ? g_R : g_S;
            if (row < N_NODES)
                *(float2*)(outp + (size_t)row * HID + col) =
                    make_float2(C[mf][nf][0] + b0, C[mf][nf][1] + b1);
            if (row + 8 < N_NODES)
                *(float2*)(outp + (size_t)(row + 8) * HID + col) =
                    make_float2(C[mf][nf][2] + b0, C[mf][nf][3] + b1);
        }
    }
}

// ---------------------------------------------------------------------------
// K3: aggln = LN(Hagg @ We2 / 16 + be2) * mask -> packed agglnP.  grid (782)
// ---------------------------------------------------------------------------
__global__ __launch_bounds__(256, 2) void k3_g(
    const float* __restrict__ be2, const float* __restrict__ gmsg,
    const float* __restrict__ bmsg, const float* __restrict__ mask)
{
    GEMM_HEAD();
    gemm_run(g_HaggP, g_HaggP, 8, g_We2P, 128, 0, m0, 8, smb, C, tid, wm, wn, lane);
    __syncthreads();
    float* lnbuf = (float*)sm;
    stage_C(C, lnbuf, wm, wn, lane);
    __syncthreads();

    const int r = tid >> 2, part = tid & 3;
    const int grow = m0 + r;
    float x[32], s = 0.f, ss = 0.f;
    #pragma unroll
    for (int j = 0; j < 32; ++j) {
        int col = part * 32 + j;
        float t = lnbuf[r * 132 + col] * (1.f / DEG) + be2[col];
        x[j] = t; s += t; ss += t * t;
    }
    s  += __shfl_xor_sync(~0u, s, 1);  s  += __shfl_xor_sync(~0u, s, 2);
    ss += __shfl_xor_sync(~0u, ss, 1); ss += __shfl_xor_sync(~0u, ss, 2);
    float mean = s * (1.f / 128.f);
    float var  = ss * (1.f / 128.f) - mean * mean;
    float inv  = rsqrtf(var + EPS);
    if (grow < N_NODES) {
        float mk = mask[grow];
        float y[32];
        #pragma unroll
        for (int j = 0; j < 32; ++j) {
            int col = part * 32 + j;
            y[j] = ((x[j] - mean) * inv * gmsg[col] + bmsg[col]) * mk;
        }
        split_store32(y, g_agglnP + ((size_t)part * N_PAD + grow) * 64);
    }
}

// ---------------------------------------------------------------------------
// K4a: H = swish([node | aggln] @ Wn1 + bn1) -> packed HP.  grid (782, 2)
// ---------------------------------------------------------------------------
__global__ __launch_bounds__(256, 2) void k4a_g(const float* __restrict__ bn1)
{
    GEMM_HEAD();
    const int n0g = blockIdx.y * 128;
    gemm_run(g_nodeP, g_agglnP, 4, g_Wn1P, 256, n0g, m0, 8, smb, C, tid, wm, wn, lane);
    __syncthreads();
    float* lnbuf = (float*)sm;
    stage_C(C, lnbuf, wm, wn, lane);
    __syncthreads();

    const int r = tid >> 2, part = tid & 3;
    const int grow = m0 + r;
    if (grow < N_NODES) {
        float y[32];
        #pragma unroll
        for (int j = 0; j < 32; ++j) {
            int col = part * 32 + j;
            y[j] = swish_fast(lnbuf[r * 132 + col] + bn1[n0g + col]);
        }
        split_store32(y, g_HP + ((size_t)((n0g >> 5) + part) * N_PAD + grow) * 64);
    }
}

// ---------------------------------------------------------------------------
// K4b: out = LN(H @ Wn2 + bn2 + node) * mask.  grid (782)
// ---------------------------------------------------------------------------
__global__ __launch_bounds__(256, 2) void k4b_g(
    const float* __restrict__ node, const float* __restrict__ bn2,
    const float* __restrict__ gnode, const float* __restrict__ bnode,
    const float* __restrict__ mask, float* __restrict__ out)
{
    GEMM_HEAD();
    gemm_run(g_HP, g_HP, 8, g_Wn2P, 128, 0, m0, 8, smb, C, tid, wm, wn, lane);
    __syncthreads();
    float* lnbuf = (float*)sm;
    stage_C(C, lnbuf, wm, wn, lane);
    __syncthreads();

    const int r = tid >> 2, part = tid & 3;
    const int grow = m0 + r;
    float x[32], s = 0.f, ss = 0.f;
    #pragma unroll
    for (int j = 0; j < 32; ++j) {
        int col = part * 32 + j;
        float res = (grow < N_NODES) ? node[(size_t)grow * DIM + col] : 0.f;
        float t = lnbuf[r * 132 + col] + bn2[col] + res;
        x[j] = t; s += t; ss += t * t;
    }
    s  += __shfl_xor_sync(~0u, s, 1);  s  += __shfl_xor_sync(~0u, s, 2);
    ss += __shfl_xor_sync(~0u, ss, 1); ss += __shfl_xor_sync(~0u, ss, 2);
    float mean = s * (1.f / 128.f);
    float var  = ss * (1.f / 128.f) - mean * mean;
    float inv  = rsqrtf(var + EPS);
    if (grow < N_NODES) {
        float mk = mask[grow];
        float* op = out + (size_t)grow * DIM + part * 32;
        #pragma unroll
        for (int q = 0; q < 8; ++q) {
            float4 o;
            int j = 4 * q, col = part * 32 + j;
            o.x = ((x[j]     - mean) * inv * gnode[col]     + bnode[col])     * mk;
            o.y = ((x[j + 1] - mean) * inv * gnode[col + 1] + bnode[col + 1]) * mk;
            o.z = ((x[j + 2] - mean) * inv * gnode[col + 2] + bnode[col + 2]) * mk;
            o.w = ((x[j + 3] - mean) * inv * gnode[col + 3] + bnode[col + 3]) * mk;
            *(float4*)(op + j) = o;
        }
    }
}

// ============================================================================
// K2F v3: edge projection GEMM (64 edges x 128 cols) + smem EP transpose +
// warp-per-node coalesced gather/swish/reduce.  grid (12500, 2), 256 thr.
// dynamic smem: max(GSTAGE 30720, EP buffer 64*132*4 = 33792) = 33792
// ============================================================================
#define K2_SMEM 33792

__global__ __launch_bounds__(256, 2) void k2f(
    const float* __restrict__ edge_feat, const int* __restrict__ senders)
{
    extern __shared__ __align__(16) char sm[];
    __shared__ int ss[64];
    const unsigned smb = (unsigned)__cvta_generic_to_shared(sm);
    const int tid = threadIdx.x;
    const int w = tid >> 5, lane = tid & 31;
    const int wm = w & 1, wn = w >> 1;

    const int e0 = blockIdx.x * 64;
    const int n0 = blockIdx.y * 128;

    // B: cp.async prepacked We1eP hi/lo into stage layout (Bh @ +10240, Bl @ +20480)
    {
        const int n = tid >> 1, h = (tid & 1) * 32;
        const char* srcB = (const char*)(g_We1eP + (size_t)(n0 + n) * 64);
        CP16(smb + 10240 + n * 80 + h,      srcB + h);
        CP16(smb + 10240 + n * 80 + h + 16, srcB + h + 16);
        CP16(smb + 20480 + n * 80 + h,      srcB + 64 + h);
        CP16(smb + 20480 + n * 80 + h + 16, srcB + 64 + h + 16);
        CPCOMMIT();
    }
    // A: edge_feat 64 rows x 32 feats, split hi/lo into Ah (@0) / Al (@+5120)
    {
        __nv_bfloat16* Ah = (__nv_bfloat16*)sm;
        __nv_bfloat16* Al = Ah + 2560;
        const int r = tid >> 2, c8 = (tid & 3) * 8;
        const float4* src = (const float4*)(edge_feat + (size_t)(e0 + r) * EDIM + c8);
        float4 f0 = src[0], f1 = src[1];
        sts_split4(Ah, Al, r * 40 + c8,     f0.x, f0.y, f0.z, f0.w);
        sts_split4(Ah, Al, r * 40 + c8 + 4, f1.x, f1.y, f1.z, f1.w);
    }
    if (tid < 64) ss[tid] = senders[e0 + tid];
    CPWAIT0();
    __syncthreads();

    float C[2][4][4];
    #pragma unroll
    for (int mf = 0; mf < 2; ++mf)
        #pragma unroll
        for (int nf = 0; nf < 4; ++nf)
            #pragma unroll
            for (int i = 0; i < 4; ++i) C[mf][nf][i] = 0.f;

    g_mma(smb, C, wm, wn, lane);

    // stage EP tile (64 x 132 fp32) over the stage buffer
    __syncthreads();
    float* EPb = (float*)sm;
    stage_C(C, EPb, wm, wn, lane);
    __syncthreads();

    // warp-per-(node, col-half): coalesced S gather + swish + register reduce
    const int node_l = w >> 1;                 // 0..3
    const int ch = w & 1;
    const int co = ch * 64 + lane * 2;         // 0..126
    const int node_g = (e0 >> 4) + node_l;
    const float2 rr = *(const float2*)(g_R + (size_t)node_g * HID + n0 + co);
    float a0 = 0.f, a1 = 0.f;
    #pragma unroll
    for (int e = 0; e < 16; ++e) {
        int snd = ss[node_l * 16 + e];
        float2 sv = *(const float2*)(g_S + (size_t)snd * HID + n0 + co);
        float2 ep = *(const float2*)&EPb[(node_l * 16 + e) * 132 + co];
        a0 += swish_fast(ep.x + sv.x + rr.x);
        a1 += swish_fast(ep.y + sv.y + rr.y);
    }
    // packed hi/lo store into g_HaggP
    {
        int gcol = n0 + co;
        int kc = gcol >> 5, kin = gcol & 31;
        size_t base = ((size_t)kc * N_PAD + node_g) * 64 + kin;
        __nv_bfloat162 hh = __floats2bfloat162_rn(a0, a1);
        __nv_bfloat162 ll = __floats2bfloat162_rn(a0 - __bfloat162float(hh.x),
                                                  a1 - __bfloat162float(hh.y));
        *(unsigned*)&g_HaggP[base]      = *(unsigned*)&hh;
        *(unsigned*)&g_HaggP[base + 32] = *(unsigned*)&ll;
    }
}

// ---------------------------------------------------------------------------
extern "C" void kernel_launch(void* const* d_in, const int* in_sizes, int n_in,
                              void* d_out, int out_size)
{
    const float* node      = (const float*)d_in[0];
    const float* edge_feat = (const float*)d_in[1];
    const float* mask      = (const float*)d_in[2];
    const float* We1       = (const float*)d_in[3];
    const float* be1       = (const float*)d_in[4];
    const float* We2       = (const float*)d_in[5];
    const float* be2       = (const float*)d_in[6];
    const float* gmsg      = (const float*)d_in[7];
    const float* bmsg      = (const float*)d_in[8];
    const float* Wn1       = (const float*)d_in[9];
    const float* bn1       = (const float*)d_in[10];
    const float* Wn2       = (const float*)d_in[11];
    const float* bn2       = (const float*)d_in[12];
    const float* gnode     = (const float*)d_in[13];
    const float* bnode     = (const float*)d_in[14];
    const int*   senders   = (const int*)d_in[15];
    float* out = (float*)d_out;

    cudaFuncSetAttribute(k1_g,  cudaFuncAttributeMaxDynamicSharedMemorySize, GSMEM);
    cudaFuncSetAttribute(k3_g,  cudaFuncAttributeMaxDynamicSharedMemorySize, GSMEM);
    cudaFuncSetAttribute(k4a_g, cudaFuncAttributeMaxDynamicSharedMemorySize, GSMEM);
    cudaFuncSetAttribute(k4b_g, cudaFuncAttributeMaxDynamicSharedMemorySize, GSMEM);

    const int mb = N_PAD / 64;   // 782

    kw_pack<<<25, 256>>>(We1, We2, Wn1, Wn2);
    k0_pack<<<mb, 256>>>(node);
    k1_g   <<<dim3(mb, 4), 256, GSMEM>>>(be1);
    k2f    <<<dim3(E_EDGES / 64, 2), 256, K2_SMEM>>>(edge_feat, senders);
    k3_g   <<<mb, 256, GSMEM>>>(be2, gmsg, bmsg, mask);
    k4a_g  <<<dim3(mb, 2), 256, GSMEM>>>(bn1);
    k4b_g  <<<mb, 256, GSMEM>>>(node, bn2, gnode, bnode, mask, out);
}

// round 8
// speedup vs baseline: 1.4369x; 1.1704x over previous
#include <cuda_runtime.h>
#include <cuda_bf16.h>
#include <math.h>

#define N_NODES 50000
#define N_PAD   50048            // 782 * 64
#define E_EDGES 800000
#define DIM     128
#define EDIM    32
#define HID     256
#define DEG     16
#define EPS     1e-5f

// ---------------- scratch (device globals; allocation-free rule) ------------
__device__ float g_S[N_NODES * HID];
__device__ float g_R[N_NODES * HID];
// packed activations: [kc][row][64 halves] = 32 hi || 32 lo  (128B per (kc,row))
__device__ __align__(16) __nv_bfloat16 g_nodeP [4ull * N_PAD * 64];
__device__ __align__(16) __nv_bfloat16 g_HaggP [8ull * N_PAD * 64];
__device__ __align__(16) __nv_bfloat16 g_agglnP[4ull * N_PAD * 64];
__device__ __align__(16) __nv_bfloat16 g_HP    [8ull * N_PAD * 64];
// packed weights: [kc][n][64 halves]
__device__ __align__(16) __nv_bfloat16 g_BP1  [4 * 512 * 64];   // [We1_top | We1_mid]
__device__ __align__(16) __nv_bfloat16 g_We1eP[256 * 64];       // We1 edge rows (K=32)
__device__ __align__(16) __nv_bfloat16 g_We2P [8 * 128 * 64];
__device__ __align__(16) __nv_bfloat16 g_Wn1P [8 * 256 * 64];
__device__ __align__(16) __nv_bfloat16 g_Wn2P [8 * 128 * 64];

__device__ __forceinline__ float swish_fast(float x) {
    float e = __expf(-x);
    return x * __fdividef(1.f, 1.f + e);
}

// single-MUFU swish: sigmoid(x) = 0.5*tanh(x/2) + 0.5
__device__ __forceinline__ float swish_tanh(float x) {
    float t;
    asm("tanh.approx.f32 %0, %1;" : "=f"(t) : "f"(x * 0.5f));
    return x * fmaf(t, 0.5f, 0.5f);
}

// ---------------- common asm helpers -----------------------------------------
__device__ __forceinline__ void mma_bf16(float (&c)[4],
                                         unsigned a0, unsigned a1, unsigned a2, unsigned a3,
                                         unsigned b0, unsigned b1) {
    asm volatile(
        "mma.sync.aligned.m16n8k16.row.col.f32.bf16.bf16.f32 "
        "{%0,%1,%2,%3}, {%4,%5,%6,%7}, {%8,%9}, {%0,%1,%2,%3};"
        : "+f"(c[0]), "+f"(c[1]), "+f"(c[2]), "+f"(c[3])
        : "r"(a0), "r"(a1), "r"(a2), "r"(a3), "r"(b0), "r"(b1));
}

__device__ __forceinline__ void ldsm4(unsigned& r0, unsigned& r1, unsigned& r2, unsigned& r3,
                                      unsigned addr) {
    asm volatile("ldmatrix.sync.aligned.m8n8.x4.shared.b16 {%0,%1,%2,%3}, [%4];"
                 : "=r"(r0), "=r"(r1), "=r"(r2), "=r"(r3) : "r"(addr));
}

#define CP16(dst, src) asm volatile("cp.async.cg.shared.global [%0], [%1], 16;" :: "r"(dst), "l"(src))
#define CPCOMMIT()     asm volatile("cp.async.commit_group;" ::: "memory")
#define CPWAIT1()      asm volatile("cp.async.wait_group 1;" ::: "memory")
#define CPWAIT0()      asm volatile("cp.async.wait_group 0;" ::: "memory")

// split 32 fp32 -> 32 hi + 32 lo bf16, store 128B at dst (16B aligned)
__device__ __forceinline__ void split_store32(const float* x, __nv_bfloat16* dst) {
    unsigned hw[16], lw[16];
    #pragma unroll
    for (int t = 0; t < 16; ++t) {
        __nv_bfloat162 h = __floats2bfloat162_rn(x[2*t], x[2*t+1]);
        __nv_bfloat162 l = __floats2bfloat162_rn(x[2*t]   - __bfloat162float(h.x),
                                                 x[2*t+1] - __bfloat162float(h.y));
        hw[t] = *(unsigned*)&h;
        lw[t] = *(unsigned*)&l;
    }
    uint4* dh = (uint4*)dst;
    uint4* dl = (uint4*)(dst + 32);
    #pragma unroll
    for (int t = 0; t < 4; ++t) {
        dh[t] = make_uint4(hw[4*t], hw[4*t+1], hw[4*t+2], hw[4*t+3]);
        dl[t] = make_uint4(lw[4*t], lw[4*t+1], lw[4*t+2], lw[4*t+3]);
    }
}

__device__ __forceinline__ void sts_split4(__nv_bfloat16* Hp, __nv_bfloat16* Lp, int off,
                                           float x0, float x1, float x2, float x3) {
    __nv_bfloat162 h01 = __floats2bfloat162_rn(x0, x1);
    __nv_bfloat162 h23 = __floats2bfloat162_rn(x2, x3);
    __nv_bfloat162 l01 = __floats2bfloat162_rn(x0 - __bfloat162float(h01.x),
                                               x1 - __bfloat162float(h01.y));
    __nv_bfloat162 l23 = __floats2bfloat162_rn(x2 - __bfloat162float(h23.x),
                                               x3 - __bfloat162float(h23.y));
    *(uint2*)(Hp + off) = make_uint2(*(unsigned*)&h01, *(unsigned*)&h23);
    *(uint2*)(Lp + off) = make_uint2(*(unsigned*)&l01, *(unsigned*)&l23);
}

// ============================================================================
// Packed GEMM: CTA tile 64(M)x128(N), K-chunks of 32, 256 threads (8 warps 2x4)
// stage: Ah[64][40] Al Bh[128][40] Bl; 80B rows (cf-free ldmatrix), 30720B
// ============================================================================
#define GSTAGE 30720
#define GSMEM  (3 * GSTAGE)      // 92160

__device__ __forceinline__ void g_ldstage(
    const __nv_bfloat16* __restrict__ AP0, const __nv_bfloat16* __restrict__ AP1,
    int splitAt, const __nv_bfloat16* __restrict__ BP, int NBW, int n0,
    int m0, int kc, unsigned smst, int tid)
{
    const __nv_bfloat16* AP = (kc < splitAt) ? AP0 : AP1;
    const int kcl = (kc < splitAt) ? kc : kc - splitAt;
    {
        const int r = tid >> 2, seg = (tid & 3) * 16;
        const char* srcA = (const char*)(AP + ((size_t)kcl * N_PAD + (m0 + r)) * 64);
        CP16(smst + r * 80 + seg,        srcA + seg);
        CP16(smst + 5120 + r * 80 + seg, srcA + 64 + seg);
    }
    {
        const int n = tid >> 1, s0 = (tid & 1) * 32;
        const char* srcB = (const char*)(BP + ((size_t)kc * NBW + n0 + n) * 64);
        CP16(smst + 10240 + n * 80 + s0,      srcB + s0);
        CP16(smst + 10240 + n * 80 + s0 + 16, srcB + s0 + 16);
        CP16(smst + 20480 + n * 80 + s0,      srcB + 64 + s0);
        CP16(smst + 20480 + n * 80 + s0 + 16, srcB + 64 + s0 + 16);
    }
}

// A at aBase (hi) / aBase+5120 (lo); B at bBase (hi) / bBase+10240 (lo)
__device__ __forceinline__ void g_mma2(unsigned aBase, unsigned bBase,
                                       float (&C)[2][4][4], int wm, int wn, int lane)
{
    const unsigned aH = aBase, aL = aBase + 5120, bH = bBase, bL = bBase + 10240;
    const unsigned aoff = (unsigned)((wm * 32 + (lane & 15)) * 80 + (lane >> 4) * 16);
    const unsigned boff = (unsigned)((wn * 32 + ((lane >> 4) & 1) * 8 + (lane & 7)) * 80
                                     + ((lane >> 3) & 1) * 16);
    #pragma unroll
    for (int ks = 0; ks < 2; ++ks) {
        const unsigned kb = ks * 32;
        unsigned ah[2][4], al[2][4];
        #pragma unroll
        for (int mf = 0; mf < 2; ++mf) {
            ldsm4(ah[mf][0], ah[mf][1], ah[mf][2], ah[mf][3], aH + aoff + mf * 16 * 80 + kb);
            ldsm4(al[mf][0], al[mf][1], al[mf][2], al[mf][3], aL + aoff + mf * 16 * 80 + kb);
        }
        #pragma unroll
        for (int p = 0; p < 2; ++p) {
            unsigned bh[4], bl[4];
            ldsm4(bh[0], bh[1], bh[2], bh[3], bH + boff + p * 16 * 80 + kb);
            ldsm4(bl[0], bl[1], bl[2], bl[3], bL + boff + p * 16 * 80 + kb);
            #pragma unroll
            for (int sub = 0; sub < 2; ++sub) {
                int nf = p * 2 + sub;
                unsigned b0h = bh[sub * 2], b1h = bh[sub * 2 + 1];
                unsigned b0l = bl[sub * 2], b1l = bl[sub * 2 + 1];
                #pragma unroll
                for (int mf = 0; mf < 2; ++mf) {
                    mma_bf16(C[mf][nf], ah[mf][0], ah[mf][1], ah[mf][2], ah[mf][3], b0h, b1h);
                    mma_bf16(C[mf][nf], ah[mf][0], ah[mf][1], ah[mf][2], ah[mf][3], b0l, b1l);
                    mma_bf16(C[mf][nf], al[mf][0], al[mf][1], al[mf][2], al[mf][3], b0h, b1h);
                }
            }
        }
    }
}

__device__ __forceinline__ void g_mma(unsigned st, float (&C)[2][4][4],
                                      int wm, int wn, int lane)
{
    g_mma2(st, st + 10240, C, wm, wn, lane);
}

__device__ __forceinline__ void gemm_run(
    const __nv_bfloat16* __restrict__ AP0, const __nv_bfloat16* __restrict__ AP1,
    int splitAt, const __nv_bfloat16* __restrict__ BP, int NBW, int n0,
    int m0, int KT, unsigned smb, float (&C)[2][4][4],
    int tid, int wm, int wn, int lane)
{
    g_ldstage(AP0, AP1, splitAt, BP, NBW, n0, m0, 0, smb, tid);          CPCOMMIT();
    g_ldstage(AP0, AP1, splitAt, BP, NBW, n0, m0, 1, smb + GSTAGE, tid); CPCOMMIT();
    for (int kc = 0; kc < KT; ++kc) {
        if (kc < KT - 1) CPWAIT1(); else CPWAIT0();
        __syncthreads();
        if (kc + 2 < KT) {
            g_ldstage(AP0, AP1, splitAt, BP, NBW, n0, m0, kc + 2,
                      smb + (unsigned)((kc + 2) % 3) * GSTAGE, tid);
            CPCOMMIT();
        }
        g_mma(smb + (unsigned)(kc % 3) * GSTAGE, C, wm, wn, lane);
    }
}

__device__ __forceinline__ void stage_C(float (&C)[2][4][4], float* lnbuf,
                                        int wm, int wn, int lane)
{
    const int gr = lane >> 2, tc = lane & 3;
    #pragma unroll
    for (int mf = 0; mf < 2; ++mf) {
        int lr = wm * 32 + mf * 16 + gr;
        #pragma unroll
        for (int nf = 0; nf < 4; ++nf) {
            int col = wn * 32 + nf * 8 + 2 * tc;
            *(float2*)&lnbuf[lr * 132 + col]       = make_float2(C[mf][nf][0], C[mf][nf][1]);
            *(float2*)&lnbuf[(lr + 8) * 132 + col] = make_float2(C[mf][nf][2], C[mf][nf][3]);
        }
    }
}

#define GEMM_HEAD()                                                            \
    extern __shared__ __align__(16) char sm[];                                 \
    const unsigned smb = (unsigned)__cvta_generic_to_shared(sm);               \
    const int tid = threadIdx.x;                                               \
    const int w = tid >> 5, lane = tid & 31;                                   \
    const int wm = w & 1, wn = w >> 1;                                         \
    const int m0 = blockIdx.x * 64;                                            \
    float C[2][4][4];                                                          \
    _Pragma("unroll") for (int mf = 0; mf < 2; ++mf)                           \
        _Pragma("unroll") for (int nf = 0; nf < 4; ++nf)                       \
            _Pragma("unroll") for (int i = 0; i < 4; ++i) C[mf][nf][i] = 0.f;

// ---------------------------------------------------------------------------
// KW: pack all weights to bf16 hi/lo tile layout.  6400 threads.
// ---------------------------------------------------------------------------
__global__ void kw_pack(const float* __restrict__ We1, const float* __restrict__ We2,
                        const float* __restrict__ Wn1, const float* __restrict__ Wn2)
{
    int idx = blockIdx.x * 256 + threadIdx.x;
    float v[32];
    __nv_bfloat16* dst;
    if (idx < 2048) {                               // BP1: [4][512]
        int kc = idx >> 9, n = idx & 511;
        int rb = (n < 256) ? kc * 32 : 128 + kc * 32;
        int c = n & 255;
        #pragma unroll
        for (int k = 0; k < 32; ++k) v[k] = We1[(rb + k) * 256 + c];
        dst = g_BP1 + (size_t)idx * 64;
    } else if (idx < 2304) {                        // We1eP: [256]
        int n = idx - 2048;
        #pragma unroll
        for (int k = 0; k < 32; ++k) v[k] = We1[(256 + k) * 256 + n];
        dst = g_We1eP + (size_t)n * 64;
    } else if (idx < 3328) {                        // We2P: [8][128]
        int t = idx - 2304, kc = t >> 7, n = t & 127;
        #pragma unroll
        for (int k = 0; k < 32; ++k) v[k] = We2[(kc * 32 + k) * 128 + n];
        dst = g_We2P + (size_t)t * 64;
    } else if (idx < 5376) {                        // Wn1P: [8][256]
        int t = idx - 3328, kc = t >> 8, n = t & 255;
        #pragma unroll
        for (int k = 0; k < 32; ++k) v[k] = Wn1[(kc * 32 + k) * 256 + n];
        dst = g_Wn1P + (size_t)t * 64;
    } else if (idx < 6400) {                        // Wn2P: [8][128]
        int t = idx - 5376, kc = t >> 7, n = t & 127;
        #pragma unroll
        for (int k = 0; k < 32; ++k) v[k] = Wn2[(kc * 32 + k) * 128 + n];
        dst = g_Wn2P + (size_t)t * 64;
    } else return;
    split_store32(v, dst);
}

// ---------------------------------------------------------------------------
// K0: pack node -> g_nodeP.  grid 782 x 256
// ---------------------------------------------------------------------------
__global__ __launch_bounds__(256) void k0_pack(const float* __restrict__ node)
{
    int r = blockIdx.x * 64 + (threadIdx.x >> 2);
    int part = threadIdx.x & 3;
    if (r >= N_NODES) return;
    const float* src = node + (size_t)r * DIM + part * 32;
    float v[32];
    #pragma unroll
    for (int q = 0; q < 8; ++q) *(float4*)&v[4 * q] = ((const float4*)src)[q];
    split_store32(v, g_nodeP + ((size_t)part * N_PAD + r) * 64);
}

// ---------------------------------------------------------------------------
// K1: S = node@We1[0:128,:], R = node@We1[128:256,:] + be1.  grid (782, 4)
// ---------------------------------------------------------------------------
__global__ __launch_bounds__(256, 2) void k1_g(const float* __restrict__ be1)
{
    GEMM_HEAD();
    const int n0g = blockIdx.y * 128;
    gemm_run(g_nodeP, g_nodeP, 4, g_BP1, 512, n0g, m0, 4, smb, C, tid, wm, wn, lane);

    const int gr = lane >> 2, tc = lane & 3;
    #pragma unroll
    for (int mf = 0; mf < 2; ++mf) {
        int row = m0 + wm * 32 + mf * 16 + gr;
        #pragma unroll
        for (int nf = 0; nf < 4; ++nf) {
            int gcol = n0g + wn * 32 + nf * 8 + 2 * tc;
            int which = gcol >> 8;
            int col = gcol & 255;
            float b0 = which ? be1[col] : 0.f;
            float b1 = which ? be1[col + 1] : 0.f;
            float* outp = which ? g_R : g_S;
            if (row < N_NODES)
                *(float2*)(outp + (size_t)row * HID + col) =
                    make_float2(C[mf][nf][0] + b0, C[mf][nf][1] + b1);
            if (row + 8 < N_NODES)
                *(float2*)(outp + (size_t)(row + 8) * HID + col) =
                    make_float2(C[mf][nf][2] + b0, C[mf][nf][3] + b1);
        }
    }
}

// ---------------------------------------------------------------------------
// K3: aggln = LN(Hagg @ We2 / 16 + be2) * mask -> packed agglnP.  grid (782)
// ---------------------------------------------------------------------------
__global__ __launch_bounds__(256, 2) void k3_g(
    const float* __restrict__ be2, const float* __restrict__ gmsg,
    const float* __restrict__ bmsg, const float* __restrict__ mask)
{
    GEMM_HEAD();
    gemm_run(g_HaggP, g_HaggP, 8, g_We2P, 128, 0, m0, 8, smb, C, tid, wm, wn, lane);
    __syncthreads();
    float* lnbuf = (float*)sm;
    stage_C(C, lnbuf, wm, wn, lane);
    __syncthreads();

    const int r = tid >> 2, part = tid & 3;
    const int grow = m0 + r;
    float x[32], s = 0.f, ss = 0.f;
    #pragma unroll
    for (int j = 0; j < 32; ++j) {
        int col = part * 32 + j;
        float t = lnbuf[r * 132 + col] * (1.f / DEG) + be2[col];
        x[j] = t; s += t; ss += t * t;
    }
    s  += __shfl_xor_sync(~0u, s, 1);  s  += __shfl_xor_sync(~0u, s, 2);
    ss += __shfl_xor_sync(~0u, ss, 1); ss += __shfl_xor_sync(~0u, ss, 2);
    float mean = s * (1.f / 128.f);
    float var  = ss * (1.f / 128.f) - mean * mean;
    float inv  = rsqrtf(var + EPS);
    if (grow < N_NODES) {
        float mk = mask[grow];
        float y[32];
        #pragma unroll
        for (int j = 0; j < 32; ++j) {
            int col = part * 32 + j;
            y[j] = ((x[j] - mean) * inv * gmsg[col] + bmsg[col]) * mk;
        }
        split_store32(y, g_agglnP + ((size_t)part * N_PAD + grow) * 64);
    }
}

// ---------------------------------------------------------------------------
// K4a: H = swish([node | aggln] @ Wn1 + bn1) -> packed HP.  grid (782, 2)
// ---------------------------------------------------------------------------
__global__ __launch_bounds__(256, 2) void k4a_g(const float* __restrict__ bn1)
{
    GEMM_HEAD();
    const int n0g = blockIdx.y * 128;
    gemm_run(g_nodeP, g_agglnP, 4, g_Wn1P, 256, n0g, m0, 8, smb, C, tid, wm, wn, lane);
    __syncthreads();
    float* lnbuf = (float*)sm;
    stage_C(C, lnbuf, wm, wn, lane);
    __syncthreads();

    const int r = tid >> 2, part = tid & 3;
    const int grow = m0 + r;
    if (grow < N_NODES) {
        float y[32];
        #pragma unroll
        for (int j = 0; j < 32; ++j) {
            int col = part * 32 + j;
            y[j] = swish_fast(lnbuf[r * 132 + col] + bn1[n0g + col]);
        }
        split_store32(y, g_HP + ((size_t)((n0g >> 5) + part) * N_PAD + grow) * 64);
    }
}

// ---------------------------------------------------------------------------
// K4b: out = LN(H @ Wn2 + bn2 + node) * mask.  grid (782)
// ---------------------------------------------------------------------------
__global__ __launch_bounds__(256, 2) void k4b_g(
    const float* __restrict__ node, const float* __restrict__ bn2,
    const float* __restrict__ gnode, const float* __restrict__ bnode,
    const float* __restrict__ mask, float* __restrict__ out)
{
    GEMM_HEAD();
    gemm_run(g_HP, g_HP, 8, g_Wn2P, 128, 0, m0, 8, smb, C, tid, wm, wn, lane);
    __syncthreads();
    float* lnbuf = (float*)sm;
    stage_C(C, lnbuf, wm, wn, lane);
    __syncthreads();

    const int r = tid >> 2, part = tid & 3;
    const int grow = m0 + r;
    float x[32], s = 0.f, ss = 0.f;
    #pragma unroll
    for (int j = 0; j < 32; ++j) {
        int col = part * 32 + j;
        float res = (grow < N_NODES) ? node[(size_t)grow * DIM + col] : 0.f;
        float t = lnbuf[r * 132 + col] + bn2[col] + res;
        x[j] = t; s += t; ss += t * t;
    }
    s  += __shfl_xor_sync(~0u, s, 1);  s  += __shfl_xor_sync(~0u, s, 2);
    ss += __shfl_xor_sync(~0u, ss, 1); ss += __shfl_xor_sync(~0u, ss, 2);
    float mean = s * (1.f / 128.f);
    float var  = ss * (1.f / 128.f) - mean * mean;
    float inv  = rsqrtf(var + EPS);
    if (grow < N_NODES) {
        float mk = mask[grow];
        float* op = out + (size_t)grow * DIM + part * 32;
        #pragma unroll
        for (int q = 0; q < 8; ++q) {
            float4 o;
            int j = 4 * q, col = part * 32 + j;
            o.x = ((x[j]     - mean) * inv * gnode[col]     + bnode[col])     * mk;
            o.y = ((x[j + 1] - mean) * inv * gnode[col + 1] + bnode[col + 1]) * mk;
            o.z = ((x[j + 2] - mean) * inv * gnode[col + 2] + bnode[col + 2]) * mk;
            o.w = ((x[j + 3] - mean) * inv * gnode[col + 3] + bnode[col + 3]) * mk;
            *(float4*)(op + j) = o;
        }
    }
}

// ============================================================================
// K2F v4: 256 edges/CTA, B staged ONCE, 4 rounds of (A -> MMA -> EP -> epilogue)
// grid (3125, 2), 256 threads, 3 CTAs/SM.
// smem: B hi/lo @0 (20480), A hi/lo @20480 (10240), EP fp32 @30720 (33792)
// ============================================================================
#define K2_B    0
#define K2_A    20480
#define K2_EP   30720
#define K2_SMEM 64512

__device__ __forceinline__ void k2_store_A(char* sm, const float* __restrict__ edge_feat,
                                           int ebase, int tid)
{
    __nv_bfloat16* Ah = (__nv_bfloat16*)(sm + K2_A);
    __nv_bfloat16* Al = Ah + 2560;
    const int r = tid >> 2, c8 = (tid & 3) * 8;
    const float4* src = (const float4*)(edge_feat + (size_t)(ebase + r) * EDIM + c8);
    float4 f0 = src[0], f1 = src[1];
    sts_split4(Ah, Al, r * 40 + c8,     f0.x, f0.y, f0.z, f0.w);
    sts_split4(Ah, Al, r * 40 + c8 + 4, f1.x, f1.y, f1.z, f1.w);
}

__global__ __launch_bounds__(256, 3) void k2f(
    const float* __restrict__ edge_feat, const int* __restrict__ senders)
{
    extern __shared__ __align__(16) char sm[];
    __shared__ int ss[256];
    const unsigned smb = (unsigned)__cvta_generic_to_shared(sm);
    const int tid = threadIdx.x;
    const int w = tid >> 5, lane = tid & 31;
    const int wm = w & 1, wn = w >> 1;

    const int e0 = blockIdx.x * 256;
    const int n0 = blockIdx.y * 128;

    // B: stage once (cp.async prepacked We1eP hi/lo)
    {
        const int n = tid >> 1, h = (tid & 1) * 32;
        const char* srcB = (const char*)(g_We1eP + (size_t)(n0 + n) * 64);
        CP16(smb + K2_B + n * 80 + h,              srcB + h);
        CP16(smb + K2_B + n * 80 + h + 16,         srcB + h + 16);
        CP16(smb + K2_B + 10240 + n * 80 + h,      srcB + 64 + h);
        CP16(smb + K2_B + 10240 + n * 80 + h + 16, srcB + 64 + h + 16);
        CPCOMMIT();
    }
    ss[tid] = senders[e0 + tid];
    k2_store_A(sm, edge_feat, e0, tid);
    CPWAIT0();
    __syncthreads();

    float* EPb = (float*)(sm + K2_EP);
    const int node_l = w >> 1;                 // 0..3 within the 64-edge round
    const int ch = w & 1;
    const int co = ch * 64 + lane * 2;         // 0..126

    #pragma unroll
    for (int g = 0; g < 4; ++g) {
        float C[2][4][4];
        #pragma unroll
        for (int mf = 0; mf < 2; ++mf)
            #pragma unroll
            for (int nf = 0; nf < 4; ++nf)
                #pragma unroll
                for (int i = 0; i < 4; ++i) C[mf][nf][i] = 0.f;

        g_mma2(smb + K2_A, smb + K2_B, C, wm, wn, lane);
        stage_C(C, EPb, wm, wn, lane);
        __syncthreads();                       // EP ready; all A/B smem reads done

        if (g < 3) k2_store_A(sm, edge_feat, e0 + (g + 1) * 64, tid);

        // epilogue: warp-per-(node, col-half), coalesced S gather, register reduce
        const int node_g = (e0 >> 4) + g * 4 + node_l;
        const float2 rr = *(const float2*)(g_R + (size_t)node_g * HID + n0 + co);
        float a0 = 0.f, a1 = 0.f;
        #pragma unroll
        for (int e = 0; e < 16; ++e) {
            int snd = ss[g * 64 + node_l * 16 + e];
            float2 sv = *(const float2*)(g_S + (size_t)snd * HID + n0 + co);
            float2 ep = *(const float2*)&EPb[(node_l * 16 + e) * 132 + co];
            a0 += swish_tanh(ep.x + sv.x + rr.x);
            a1 += swish_tanh(ep.y + sv.y + rr.y);
        }
        {
            int gcol = n0 + co;
            int kc = gcol >> 5, kin = gcol & 31;
            size_t base = ((size_t)kc * N_PAD + node_g) * 64 + kin;
            __nv_bfloat162 hh = __floats2bfloat162_rn(a0, a1);
            __nv_bfloat162 ll = __floats2bfloat162_rn(a0 - __bfloat162float(hh.x),
                                                      a1 - __bfloat162float(hh.y));
            *(unsigned*)&g_HaggP[base]      = *(unsigned*)&hh;
            *(unsigned*)&g_HaggP[base + 32] = *(unsigned*)&ll;
        }
        if (g < 3) __syncthreads();            // A staged + EP reads done before next round
    }
}

// ---------------------------------------------------------------------------
extern "C" void kernel_launch(void* const* d_in, const int* in_sizes, int n_in,
                              void* d_out, int out_size)
{
    const float* node      = (const float*)d_in[0];
    const float* edge_feat = (const float*)d_in[1];
    const float* mask      = (const float*)d_in[2];
    const float* We1       = (const float*)d_in[3];
    const float* be1       = (const float*)d_in[4];
    const float* We2       = (const float*)d_in[5];
    const float* be2       = (const float*)d_in[6];
    const float* gmsg      = (const float*)d_in[7];
    const float* bmsg      = (const float*)d_in[8];
    const float* Wn1       = (const float*)d_in[9];
    const float* bn1       = (const float*)d_in[10];
    const float* Wn2       = (const float*)d_in[11];
    const float* bn2       = (const float*)d_in[12];
    const float* gnode     = (const float*)d_in[13];
    const float* bnode     = (const float*)d_in[14];
    const int*   senders   = (const int*)d_in[15];
    float* out = (float*)d_out;

    cudaFuncSetAttribute(k1_g,  cudaFuncAttributeMaxDynamicSharedMemorySize, GSMEM);
    cudaFuncSetAttribute(k2f,   cudaFuncAttributeMaxDynamicSharedMemorySize, K2_SMEM);
    cudaFuncSetAttribute(k3_g,  cudaFuncAttributeMaxDynamicSharedMemorySize, GSMEM);
    cudaFuncSetAttribute(k4a_g, cudaFuncAttributeMaxDynamicSharedMemorySize, GSMEM);
    cudaFuncSetAttribute(k4b_g, cudaFuncAttributeMaxDynamicSharedMemorySize, GSMEM);

    const int mb = N_PAD / 64;   // 782

    kw_pack<<<25, 256>>>(We1, We2, Wn1, Wn2);
    k0_pack<<<mb, 256>>>(node);
    k1_g   <<<dim3(mb, 4), 256, GSMEM>>>(be1);
    k2f    <<<dim3(E_EDGES / 256, 2), 256, K2_SMEM>>>(edge_feat, senders);
    k3_g   <<<mb, 256, GSMEM>>>(be2, gmsg, bmsg, mask);
    k4a_g  <<<dim3(mb, 2), 256, GSMEM>>>(bn1);
    k4b_g  <<<mb, 256, GSMEM>>>(node, bn2, gnode, bnode, mask, out);
}

// round 13
// speedup vs baseline: 1.6401x; 1.1414x over previous
#include <cuda_runtime.h>
#include <cuda_bf16.h>
#include <math.h>

#define N_NODES 50000
#define N_PAD   50048            // 782 * 64
#define E_EDGES 800000
#define DIM     128
#define EDIM    32
#define HID     256
#define DEG     16
#define EPS     1e-5f

// ---------------- scratch (device globals; allocation-free rule) ------------
__device__ float g_S[N_NODES * HID];
__device__ float g_R[N_NODES * HID];
// packed activations: [kc][row][64 halves] = 32 hi || 32 lo  (128B per (kc,row))
__device__ __align__(16) __nv_bfloat16 g_nodeP [4ull * N_PAD * 64];
__device__ __align__(16) __nv_bfloat16 g_HaggP [8ull * N_PAD * 64];
__device__ __align__(16) __nv_bfloat16 g_agglnP[4ull * N_PAD * 64];
__device__ __align__(16) __nv_bfloat16 g_HP    [8ull * N_PAD * 64];
// packed weights: [kc][n][64 halves]
__device__ __align__(16) __nv_bfloat16 g_BP1  [4 * 512 * 64];   // [We1_top | We1_mid]
__device__ __align__(16) __nv_bfloat16 g_We1eP[256 * 64];       // We1 edge rows (K=32)
__device__ __align__(16) __nv_bfloat16 g_We2P [8 * 128 * 64];
__device__ __align__(16) __nv_bfloat16 g_Wn1P [8 * 256 * 64];
__device__ __align__(16) __nv_bfloat16 g_Wn2P [8 * 128 * 64];

__device__ __forceinline__ float swish_fast(float x) {
    float e = __expf(-x);
    return x * __fdividef(1.f, 1.f + e);
}

// single-MUFU swish: sigmoid(x) = 0.5*tanh(x/2) + 0.5
__device__ __forceinline__ float swish_tanh(float x) {
    float t;
    asm("tanh.approx.f32 %0, %1;" : "=f"(t) : "f"(x * 0.5f));
    return x * fmaf(t, 0.5f, 0.5f);
}

// ---------------- common asm helpers -----------------------------------------
__device__ __forceinline__ void mma_bf16(float (&c)[4],
                                         unsigned a0, unsigned a1, unsigned a2, unsigned a3,
                                         unsigned b0, unsigned b1) {
    asm volatile(
        "mma.sync.aligned.m16n8k16.row.col.f32.bf16.bf16.f32 "
        "{%0,%1,%2,%3}, {%4,%5,%6,%7}, {%8,%9}, {%0,%1,%2,%3};"
        : "+f"(c[0]), "+f"(c[1]), "+f"(c[2]), "+f"(c[3])
        : "r"(a0), "r"(a1), "r"(a2), "r"(a3), "r"(b0), "r"(b1));
}

__device__ __forceinline__ void ldsm4(unsigned& r0, unsigned& r1, unsigned& r2, unsigned& r3,
                                      unsigned addr) {
    asm volatile("ldmatrix.sync.aligned.m8n8.x4.shared.b16 {%0,%1,%2,%3}, [%4];"
                 : "=r"(r0), "=r"(r1), "=r"(r2), "=r"(r3) : "r"(addr));
}

#define CP16(dst, src) asm volatile("cp.async.cg.shared.global [%0], [%1], 16;" :: "r"(dst), "l"(src))
#define CPCOMMIT()     asm volatile("cp.async.commit_group;" ::: "memory")
#define CPWAIT1()      asm volatile("cp.async.wait_group 1;" ::: "memory")
#define CPWAIT0()      asm volatile("cp.async.wait_group 0;" ::: "memory")

// split 32 fp32 -> 32 hi + 32 lo bf16, store 128B at dst (16B aligned)
__device__ __forceinline__ void split_store32(const float* x, __nv_bfloat16* dst) {
    unsigned hw[16], lw[16];
    #pragma unroll
    for (int t = 0; t < 16; ++t) {
        __nv_bfloat162 h = __floats2bfloat162_rn(x[2*t], x[2*t+1]);
        __nv_bfloat162 l = __floats2bfloat162_rn(x[2*t]   - __bfloat162float(h.x),
                                                 x[2*t+1] - __bfloat162float(h.y));
        hw[t] = *(unsigned*)&h;
        lw[t] = *(unsigned*)&l;
    }
    uint4* dh = (uint4*)dst;
    uint4* dl = (uint4*)(dst + 32);
    #pragma unroll
    for (int t = 0; t < 4; ++t) {
        dh[t] = make_uint4(hw[4*t], hw[4*t+1], hw[4*t+2], hw[4*t+3]);
        dl[t] = make_uint4(lw[4*t], lw[4*t+1], lw[4*t+2], lw[4*t+3]);
    }
}

// ============================================================================
// Packed GEMM: CTA tile 64(M)x128(N), K-chunks of 32, 256 threads (8 warps 2x4)
// stage: Ah[64][40] Al Bh[128][40] Bl; 80B rows (cf-free ldmatrix), 30720B
// 2-stage ring, 3 CTAs/SM.
// ============================================================================
#define GSTAGE 30720
#define GSMEM  (2 * GSTAGE)      // 61440

__device__ __forceinline__ void g_ldstage(
    const __nv_bfloat16* __restrict__ AP0, const __nv_bfloat16* __restrict__ AP1,
    int splitAt, const __nv_bfloat16* __restrict__ BP, int NBW, int n0,
    int m0, int kc, unsigned smst, int tid)
{
    const __nv_bfloat16* AP = (kc < splitAt) ? AP0 : AP1;
    const int kcl = (kc < splitAt) ? kc : kc - splitAt;
    {
        const int r = tid >> 2, seg = (tid & 3) * 16;
        const char* srcA = (const char*)(AP + ((size_t)kcl * N_PAD + (m0 + r)) * 64);
        CP16(smst + r * 80 + seg,        srcA + seg);
        CP16(smst + 5120 + r * 80 + seg, srcA + 64 + seg);
    }
    {
        const int n = tid >> 1, s0 = (tid & 1) * 32;
        const char* srcB = (const char*)(BP + ((size_t)kc * NBW + n0 + n) * 64);
        CP16(smst + 10240 + n * 80 + s0,      srcB + s0);
        CP16(smst + 10240 + n * 80 + s0 + 16, srcB + s0 + 16);
        CP16(smst + 20480 + n * 80 + s0,      srcB + 64 + s0);
        CP16(smst + 20480 + n * 80 + s0 + 16, srcB + 64 + s0 + 16);
    }
}

// 3-term split mma on a stage (A hi/lo @ st, st+5120; B hi/lo @ st+10240, st+20480)
__device__ __forceinline__ void g_mma(unsigned st, float (&C)[2][4][4],
                                      int wm, int wn, int lane)
{
    const unsigned aH = st, aL = st + 5120, bH = st + 10240, bL = st + 20480;
    const unsigned aoff = (unsigned)((wm * 32 + (lane & 15)) * 80 + (lane >> 4) * 16);
    const unsigned boff = (unsigned)((wn * 32 + ((lane >> 4) & 1) * 8 + (lane & 7)) * 80
                                     + ((lane >> 3) & 1) * 16);
    #pragma unroll
    for (int ks = 0; ks < 2; ++ks) {
        const unsigned kb = ks * 32;
        unsigned ah[2][4], al[2][4];
        #pragma unroll
        for (int mf = 0; mf < 2; ++mf) {
            ldsm4(ah[mf][0], ah[mf][1], ah[mf][2], ah[mf][3], aH + aoff + mf * 16 * 80 + kb);
            ldsm4(al[mf][0], al[mf][1], al[mf][2], al[mf][3], aL + aoff + mf * 16 * 80 + kb);
        }
        #pragma unroll
        for (int p = 0; p < 2; ++p) {
            unsigned bh[4], bl[4];
            ldsm4(bh[0], bh[1], bh[2], bh[3], bH + boff + p * 16 * 80 + kb);
            ldsm4(bl[0], bl[1], bl[2], bl[3], bL + boff + p * 16 * 80 + kb);
            #pragma unroll
            for (int sub = 0; sub < 2; ++sub) {
                int nf = p * 2 + sub;
                unsigned b0h = bh[sub * 2], b1h = bh[sub * 2 + 1];
                unsigned b0l = bl[sub * 2], b1l = bl[sub * 2 + 1];
                #pragma unroll
                for (int mf = 0; mf < 2; ++mf) {
                    mma_bf16(C[mf][nf], ah[mf][0], ah[mf][1], ah[mf][2], ah[mf][3], b0h, b1h);
                    mma_bf16(C[mf][nf], ah[mf][0], ah[mf][1], ah[mf][2], ah[mf][3], b0l, b1l);
                    mma_bf16(C[mf][nf], al[mf][0], al[mf][1], al[mf][2], al[mf][3], b0h, b1h);
                }
            }
        }
    }
}

// 2-stage ring pipeline
__device__ __forceinline__ void gemm_run(
    const __nv_bfloat16* __restrict__ AP0, const __nv_bfloat16* __restrict__ AP1,
    int splitAt, const __nv_bfloat16* __restrict__ BP, int NBW, int n0,
    int m0, int KT, unsigned smb, float (&C)[2][4][4],
    int tid, int wm, int wn, int lane)
{
    g_ldstage(AP0, AP1, splitAt, BP, NBW, n0, m0, 0, smb, tid);
    CPCOMMIT();
    for (int kc = 0; kc < KT; ++kc) {
        if (kc + 1 < KT) {
            g_ldstage(AP0, AP1, splitAt, BP, NBW, n0, m0, kc + 1,
                      smb + (unsigned)((kc + 1) & 1) * GSTAGE, tid);
            CPCOMMIT();
            CPWAIT1();
        } else {
            CPWAIT0();
        }
        __syncthreads();
        g_mma(smb + (unsigned)(kc & 1) * GSTAGE, C, wm, wn, lane);
        __syncthreads();
    }
}

__device__ __forceinline__ void stage_C(float (&C)[2][4][4], float* lnbuf,
                                        int wm, int wn, int lane)
{
    const int gr = lane >> 2, tc = lane & 3;
    #pragma unroll
    for (int mf = 0; mf < 2; ++mf) {
        int lr = wm * 32 + mf * 16 + gr;
        #pragma unroll
        for (int nf = 0; nf < 4; ++nf) {
            int col = wn * 32 + nf * 8 + 2 * tc;
            *(float2*)&lnbuf[lr * 132 + col]       = make_float2(C[mf][nf][0], C[mf][nf][1]);
            *(float2*)&lnbuf[(lr + 8) * 132 + col] = make_float2(C[mf][nf][2], C[mf][nf][3]);
        }
    }
}

#define GEMM_HEAD()                                                            \
    extern __shared__ __align__(16) char sm[];                                 \
    const unsigned smb = (unsigned)__cvta_generic_to_shared(sm);               \
    const int tid = threadIdx.x;                                               \
    const int w = tid >> 5, lane = tid & 31;                                   \
    const int wm = w & 1, wn = w >> 1;                                         \
    const int m0 = blockIdx.x * 64;                                            \
    float C[2][4][4];                                                          \
    _Pragma("unroll") for (int mf = 0; mf < 2; ++mf)                           \
        _Pragma("unroll") for (int nf = 0; nf < 4; ++nf)                       \
            _Pragma("unroll") for (int i = 0; i < 4; ++i) C[mf][nf][i] = 0.f;

// ---------------------------------------------------------------------------
// KW: pack all weights to bf16 hi/lo tile layout.
// ---------------------------------------------------------------------------
__global__ void kw_pack(const float* __restrict__ We1, const float* __restrict__ We2,
                        const float* __restrict__ Wn1, const float* __restrict__ Wn2)
{
    int idx = blockIdx.x * 256 + threadIdx.x;
    float v[32];
    __nv_bfloat16* dst;
    if (idx < 2048) {                               // BP1: [4][512]
        int kc = idx >> 9, n = idx & 511;
        int rb = (n < 256) ? kc * 32 : 128 + kc * 32;
        int c = n & 255;
        #pragma unroll
        for (int k = 0; k < 32; ++k) v[k] = We1[(rb + k) * 256 + c];
        dst = g_BP1 + (size_t)idx * 64;
    } else if (idx < 2304) {                        // We1eP: [256]
        int n = idx - 2048;
        #pragma unroll
        for (int k = 0; k < 32; ++k) v[k] = We1[(256 + k) * 256 + n];
        dst = g_We1eP + (size_t)n * 64;
    } else if (idx < 3328) {                        // We2P: [8][128]
        int t = idx - 2304, kc = t >> 7, n = t & 127;
        #pragma unroll
        for (int k = 0; k < 32; ++k) v[k] = We2[(kc * 32 + k) * 128 + n];
        dst = g_We2P + (size_t)t * 64;
    } else if (idx < 5376) {                        // Wn1P: [8][256]
        int t = idx - 3328, kc = t >> 8, n = t & 255;
        #pragma unroll
        for (int k = 0; k < 32; ++k) v[k] = Wn1[(kc * 32 + k) * 256 + n];
        dst = g_Wn1P + (size_t)t * 64;
    } else if (idx < 6400) {                        // Wn2P: [8][128]
        int t = idx - 5376, kc = t >> 7, n = t & 127;
        #pragma unroll
        for (int k = 0; k < 32; ++k) v[k] = Wn2[(kc * 32 + k) * 128 + n];
        dst = g_Wn2P + (size_t)t * 64;
    } else return;
    split_store32(v, dst);
}

// ---------------------------------------------------------------------------
// K0: pack node -> g_nodeP.  grid 782 x 256
// ---------------------------------------------------------------------------
__global__ __launch_bounds__(256) void k0_pack(const float* __restrict__ node)
{
    int r = blockIdx.x * 64 + (threadIdx.x >> 2);
    int part = threadIdx.x & 3;
    if (r >= N_NODES) return;
    const float* src = node + (size_t)r * DIM + part * 32;
    float v[32];
    #pragma unroll
    for (int q = 0; q < 8; ++q) *(float4*)&v[4 * q] = ((const float4*)src)[q];
    split_store32(v, g_nodeP + ((size_t)part * N_PAD + r) * 64);
}

// ---------------------------------------------------------------------------
// K1: S = node@We1[0:128,:], R = node@We1[128:256,:] + be1.  grid (782, 4)
// ---------------------------------------------------------------------------
__global__ __launch_bounds__(256, 3) void k1_g(const float* __restrict__ be1)
{
    GEMM_HEAD();
    const int n0g = blockIdx.y * 128;
    gemm_run(g_nodeP, g_nodeP, 4, g_BP1, 512, n0g, m0, 4, smb, C, tid, wm, wn, lane);

    const int gr = lane >> 2, tc = lane & 3;
    #pragma unroll
    for (int mf = 0; mf < 2; ++mf) {
        int row = m0 + wm * 32 + mf * 16 + gr;
        #pragma unroll
        for (int nf = 0; nf < 4; ++nf) {
            int gcol = n0g + wn * 32 + nf * 8 + 2 * tc;
            int which = gcol >> 8;
            int col = gcol & 255;
            float b0 = which ? be1[col] : 0.f;
            float b1 = which ? be1[col + 1] : 0.f;
            float* outp = which ? g_R : g_S;
            if (row < N_NODES)
                *(float2*)(outp + (size_t)row * HID + col) =
                    make_float2(C[mf][nf][0] + b0, C[mf][nf][1] + b1);
            if (row + 8 < N_NODES)
                *(float2*)(outp + (size_t)(row + 8) * HID + col) =
                    make_float2(C[mf][nf][2] + b0, C[mf][nf][3] + b1);
        }
    }
}

// ---------------------------------------------------------------------------
// K3: aggln = LN(Hagg @ We2 / 16 + be2) * mask -> packed agglnP.  grid (782)
// ---------------------------------------------------------------------------
__global__ __launch_bounds__(256, 3) void k3_g(
    const float* __restrict__ be2, const float* __restrict__ gmsg,
    const float* __restrict__ bmsg, const float* __restrict__ mask)
{
    GEMM_HEAD();
    gemm_run(g_HaggP, g_HaggP, 8, g_We2P, 128, 0, m0, 8, smb, C, tid, wm, wn, lane);
    float* lnbuf = (float*)sm;
    stage_C(C, lnbuf, wm, wn, lane);
    __syncthreads();

    const int r = tid >> 2, part = tid & 3;
    const int grow = m0 + r;
    float x[32], s = 0.f, ss = 0.f;
    #pragma unroll
    for (int j = 0; j < 32; ++j) {
        int col = part * 32 + j;
        float t = lnbuf[r * 132 + col] * (1.f / DEG) + be2[col];
        x[j] = t; s += t; ss += t * t;
    }
    s  += __shfl_xor_sync(~0u, s, 1);  s  += __shfl_xor_sync(~0u, s, 2);
    ss += __shfl_xor_sync(~0u, ss, 1); ss += __shfl_xor_sync(~0u, ss, 2);
    float mean = s * (1.f / 128.f);
    float var  = ss * (1.f / 128.f) - mean * mean;
    float inv  = rsqrtf(var + EPS);
    if (grow < N_NODES) {
        float mk = mask[grow];
        float y[32];
        #pragma unroll
        for (int j = 0; j < 32; ++j) {
            int col = part * 32 + j;
            y[j] = ((x[j] - mean) * inv * gmsg[col] + bmsg[col]) * mk;
        }
        split_store32(y, g_agglnP + ((size_t)part * N_PAD + grow) * 64);
    }
}

// ---------------------------------------------------------------------------
// K4a: H = swish([node | aggln] @ Wn1 + bn1) -> packed HP.  grid (782, 2)
// ---------------------------------------------------------------------------
__global__ __launch_bounds__(256, 3) void k4a_g(const float* __restrict__ bn1)
{
    GEMM_HEAD();
    const int n0g = blockIdx.y * 128;
    gemm_run(g_nodeP, g_agglnP, 4, g_Wn1P, 256, n0g, m0, 8, smb, C, tid, wm, wn, lane);
    float* lnbuf = (float*)sm;
    stage_C(C, lnbuf, wm, wn, lane);
    __syncthreads();

    const int r = tid >> 2, part = tid & 3;
    const int grow = m0 + r;
    if (grow < N_NODES) {
        float y[32];
        #pragma unroll
        for (int j = 0; j < 32; ++j) {
            int col = part * 32 + j;
            y[j] = swish_fast(lnbuf[r * 132 + col] + bn1[n0g + col]);
        }
        split_store32(y, g_HP + ((size_t)((n0g >> 5) + part) * N_PAD + grow) * 64);
    }
}

// ---------------------------------------------------------------------------
// K4b: out = LN(H @ Wn2 + bn2 + node) * mask.  grid (782)
// ---------------------------------------------------------------------------
__global__ __launch_bounds__(256, 3) void k4b_g(
    const float* __restrict__ node, const float* __restrict__ bn2,
    const float* __restrict__ gnode, const float* __restrict__ bnode,
    const float* __restrict__ mask, float* __restrict__ out)
{
    GEMM_HEAD();
    gemm_run(g_HP, g_HP, 8, g_Wn2P, 128, 0, m0, 8, smb, C, tid, wm, wn, lane);
    float* lnbuf = (float*)sm;
    stage_C(C, lnbuf, wm, wn, lane);
    __syncthreads();

    const int r = tid >> 2, part = tid & 3;
    const int grow = m0 + r;
    float x[32], s = 0.f, ss = 0.f;
    #pragma unroll
    for (int j = 0; j < 32; ++j) {
        int col = part * 32 + j;
        float res = (grow < N_NODES) ? node[(size_t)grow * DIM + col] : 0.f;
        float t = lnbuf[r * 132 + col] + bn2[col] + res;
        x[j] = t; s += t; ss += t * t;
    }
    s  += __shfl_xor_sync(~0u, s, 1);  s  += __shfl_xor_sync(~0u, s, 2);
    ss += __shfl_xor_sync(~0u, ss, 1); ss += __shfl_xor_sync(~0u, ss, 2);
    float mean = s * (1.f / 128.f);
    float var  = ss * (1.f / 128.f) - mean * mean;
    float inv  = rsqrtf(var + EPS);
    if (grow < N_NODES) {
        float mk = mask[grow];
        float* op = out + (size_t)grow * DIM + part * 32;
        #pragma unroll
        for (int q = 0; q < 8; ++q) {
            float4 o;
            int j = 4 * q, col = part * 32 + j;
            o.x = ((x[j]     - mean) * inv * gnode[col]     + bnode[col])     * mk;
            o.y = ((x[j + 1] - mean) * inv * gnode[col + 1] + bnode[col + 1]) * mk;
            o.z = ((x[j + 2] - mean) * inv * gnode[col + 2] + bnode[col + 2]) * mk;
            o.w = ((x[j + 3] - mean) * inv * gnode[col + 3] + bnode[col + 3]) * mk;
            *(float4*)(op + j) = o;
        }
    }
}

// ============================================================================
// K2F v5: 256 edges/CTA, SINGLE-term bf16 MMA (EP is bf16-grade: measured
// 7.9e-5 final in rounds 2-3), bf16 EP smem buffer.  grid (3125, 2), 256 thr.
// smem: Bh @0 (10240), Ah @10240 (5120), EP bf16x2 @15360 (64 x 68 words, 17408)
// ============================================================================
#define K2_B    0
#define K2_A    10240
#define K2_EP   15360
#define K2_SMEM 32768

__device__ __forceinline__ void k2_store_A(char* sm, const float* __restrict__ edge_feat,
                                           int ebase, int tid)
{
    __nv_bfloat16* Ah = (__nv_bfloat16*)(sm + K2_A);
    const int r = tid >> 2, c8 = (tid & 3) * 8;
    const float4* src = (const float4*)(edge_feat + (size_t)(ebase + r) * EDIM + c8);
    float4 f0 = src[0], f1 = src[1];
    __nv_bfloat162 h0 = __floats2bfloat162_rn(f0.x, f0.y);
    __nv_bfloat162 h1 = __floats2bfloat162_rn(f0.z, f0.w);
    __nv_bfloat162 h2 = __floats2bfloat162_rn(f1.x, f1.y);
    __nv_bfloat162 h3 = __floats2bfloat162_rn(f1.z, f1.w);
    *(uint4*)(Ah + r * 40 + c8) = make_uint4(*(unsigned*)&h0, *(unsigned*)&h1,
                                             *(unsigned*)&h2, *(unsigned*)&h3);
}

// single-term mma: A hi @ aBase, B hi @ bBase
__device__ __forceinline__ void g_mma1(unsigned aBase, unsigned bBase,
                                       float (&C)[2][4][4], int wm, int wn, int lane)
{
    const unsigned aoff = (unsigned)((wm * 32 + (lane & 15)) * 80 + (lane >> 4) * 16);
    const unsigned boff = (unsigned)((wn * 32 + ((lane >> 4) & 1) * 8 + (lane & 7)) * 80
                                     + ((lane >> 3) & 1) * 16);
    #pragma unroll
    for (int ks = 0; ks < 2; ++ks) {
        const unsigned kb = ks * 32;
        unsigned ah[2][4];
        #pragma unroll
        for (int mf = 0; mf < 2; ++mf)
            ldsm4(ah[mf][0], ah[mf][1], ah[mf][2], ah[mf][3],
                  aBase + aoff + mf * 16 * 80 + kb);
        #pragma unroll
        for (int p = 0; p < 2; ++p) {
            unsigned bh[4];
            ldsm4(bh[0], bh[1], bh[2], bh[3], bBase + boff + p * 16 * 80 + kb);
            #pragma unroll
            for (int sub = 0; sub < 2; ++sub) {
                int nf = p * 2 + sub;
                #pragma unroll
                for (int mf = 0; mf < 2; ++mf)
                    mma_bf16(C[mf][nf], ah[mf][0], ah[mf][1], ah[mf][2], ah[mf][3],
                             bh[sub * 2], bh[sub * 2 + 1]);
            }
        }
    }
}

// C -> bf16x2 EP buffer, stride 68 words (banks 4*gr+tc: conflict-free)
__device__ __forceinline__ void stage_C_bf16(float (&C)[2][4][4], unsigned* EPw,
                                             int wm, int wn, int lane)
{
    const int gr = lane >> 2, tc = lane & 3;
    #pragma unroll
    for (int mf = 0; mf < 2; ++mf) {
        int lr = wm * 32 + mf * 16 + gr;
        #pragma unroll
        for (int nf = 0; nf < 4; ++nf) {
            int wrd = wn * 16 + nf * 4 + tc;
            __nv_bfloat162 a = __floats2bfloat162_rn(C[mf][nf][0], C[mf][nf][1]);
            __nv_bfloat162 b = __floats2bfloat162_rn(C[mf][nf][2], C[mf][nf][3]);
            EPw[lr * 68 + wrd]       = *(unsigned*)&a;
            EPw[(lr + 8) * 68 + wrd] = *(unsigned*)&b;
        }
    }
}

__global__ __launch_bounds__(256, 4) void k2f(
    const float* __restrict__ edge_feat, const int* __restrict__ senders)
{
    extern __shared__ __align__(16) char sm[];
    __shared__ int ss[256];
    const unsigned smb = (unsigned)__cvta_generic_to_shared(sm);
    const int tid = threadIdx.x;
    const int w = tid >> 5, lane = tid & 31;
    const int wm = w & 1, wn = w >> 1;

    const int e0 = blockIdx.x * 256;
    const int n0 = blockIdx.y * 128;

    // B hi: stage once (first 64B of each packed We1eP row)
    {
        const int n = tid >> 1, h = (tid & 1) * 32;
        const char* srcB = (const char*)(g_We1eP + (size_t)(n0 + n) * 64);
        CP16(smb + K2_B + n * 80 + h,      srcB + h);
        CP16(smb + K2_B + n * 80 + h + 16, srcB + h + 16);
        CPCOMMIT();
    }
    ss[tid] = senders[e0 + tid];
    k2_store_A(sm, edge_feat, e0, tid);
    CPWAIT0();
    __syncthreads();

    unsigned* EPw = (unsigned*)(sm + K2_EP);
    const int node_l = w >> 1;                 // 0..3 within the 64-edge round
    const int ch = w & 1;
    const int co = ch * 64 + lane * 2;         // 0..126

    #pragma unroll
    for (int g = 0; g < 4; ++g) {
        float C[2][4][4];
        #pragma unroll
        for (int mf = 0; mf < 2; ++mf)
            #pragma unroll
            for (int nf = 0; nf < 4; ++nf)
                #pragma unroll
                for (int i = 0; i < 4; ++i) C[mf][nf][i] = 0.f;

        g_mma1(smb + K2_A, smb + K2_B, C, wm, wn, lane);
        stage_C_bf16(C, EPw, wm, wn, lane);
        __syncthreads();                       // EP ready; A reads done

        if (g < 3) k2_store_A(sm, edge_feat, e0 + (g + 1) * 64, tid);

        // epilogue: warp-per-(node, col-half), coalesced S gather, register reduce
        const int node_g = (e0 >> 4) + g * 4 + node_l;
        const float2 rr = *(const float2*)(g_R + (size_t)node_g * HID + n0 + co);
        float a0 = 0.f, a1 = 0.f;
        #pragma unroll
        for (int e = 0; e < 16; ++e) {
            int snd = ss[g * 64 + node_l * 16 + e];
            float2 sv = *(const float2*)(g_S + (size_t)snd * HID + n0 + co);
            unsigned epu = EPw[(node_l * 16 + e) * 68 + ch * 32 + lane];
            __nv_bfloat162 ep = *(__nv_bfloat162*)&epu;
            a0 += swish_tanh(__bfloat162float(ep.x) + sv.x + rr.x);
            a1 += swish_tanh(__bfloat162float(ep.y) + sv.y + rr.y);
        }
        {
            int gcol = n0 + co;
            int kc = gcol >> 5, kin = gcol & 31;
            size_t base = ((size_t)kc * N_PAD + node_g) * 64 + kin;
            __nv_bfloat162 hh = __floats2bfloat162_rn(a0, a1);
            __nv_bfloat162 ll = __floats2bfloat162_rn(a0 - __bfloat162float(hh.x),
                                                      a1 - __bfloat162float(hh.y));
            *(unsigned*)&g_HaggP[base]      = *(unsigned*)&hh;
            *(unsigned*)&g_HaggP[base + 32] = *(unsigned*)&ll;
        }
        if (g < 3) __syncthreads();            // A staged + EP reads done before next round
    }
}

// ---------------------------------------------------------------------------
extern "C" void kernel_launch(void* const* d_in, const int* in_sizes, int n_in,
                              void* d_out, int out_size)
{
    const float* node      = (const float*)d_in[0];
    const float* edge_feat = (const float*)d_in[1];
    const float* mask      = (const float*)d_in[2];
    const float* We1       = (const float*)d_in[3];
    const float* be1       = (const float*)d_in[4];
    const float* We2       = (const float*)d_in[5];
    const float* be2       = (const float*)d_in[6];
    const float* gmsg      = (const float*)d_in[7];
    const float* bmsg      = (const float*)d_in[8];
    const float* Wn1       = (const float*)d_in[9];
    const float* bn1       = (const float*)d_in[10];
    const float* Wn2       = (const float*)d_in[11];
    const float* bn2       = (const float*)d_in[12];
    const float* gnode     = (const float*)d_in[13];
    const float* bnode     = (const float*)d_in[14];
    const int*   senders   = (const int*)d_in[15];
    float* out = (float*)d_out;

    cudaFuncSetAttribute(k1_g,  cudaFuncAttributeMaxDynamicSharedMemorySize, GSMEM);
    cudaFuncSetAttribute(k2f,   cudaFuncAttributeMaxDynamicSharedMemorySize, K2_SMEM);
    cudaFuncSetAttribute(k3_g,  cudaFuncAttributeMaxDynamicSharedMemorySize, GSMEM);
    cudaFuncSetAttribute(k4a_g, cudaFuncAttributeMaxDynamicSharedMemorySize, GSMEM);
    cudaFuncSetAttribute(k4b_g, cudaFuncAttributeMaxDynamicSharedMemorySize, GSMEM);

    const int mb = N_PAD / 64;   // 782

    kw_pack<<<25, 256>>>(We1, We2, Wn1, Wn2);
    k0_pack<<<mb, 256>>>(node);
    k1_g   <<<dim3(mb, 4), 256, GSMEM>>>(be1);
    k2f    <<<dim3(E_EDGES / 256, 2), 256, K2_SMEM>>>(edge_feat, senders);
    k3_g   <<<mb, 256, GSMEM>>>(be2, gmsg, bmsg, mask);
    k4a_g  <<<dim3(mb, 2), 256, GSMEM>>>(bn1);
    k4b_g  <<<mb, 256, GSMEM>>>(node, bn2, gnode, bnode, mask, out);
}

// round 15
// speedup vs baseline: 1.6858x; 1.0278x over previous
#include <cuda_runtime.h>
#include <cuda_bf16.h>
#include <math.h>

#define N_NODES 50000
#define N_PAD   50048            // 782 * 64
#define E_EDGES 800000
#define DIM     128
#define EDIM    32
#define HID     256
#define DEG     16
#define EPS     1e-5f

// ---------------- scratch (device globals; allocation-free rule) ------------
__device__ __align__(16) __nv_bfloat16 g_Sb[N_NODES * HID];   // S in bf16 (gather table)
__device__ float g_R[N_NODES * HID];
// packed activations: [kc][row][64 halves] = 32 hi || 32 lo  (128B per (kc,row))
__device__ __align__(16) __nv_bfloat16 g_nodeP [4ull * N_PAD * 64];
__device__ __align__(16) __nv_bfloat16 g_HaggP [8ull * N_PAD * 64];
__device__ __align__(16) __nv_bfloat16 g_agglnP[4ull * N_PAD * 64];
__device__ __align__(16) __nv_bfloat16 g_HP    [8ull * N_PAD * 64];
// packed weights: [kc][n][64 halves]
__device__ __align__(16) __nv_bfloat16 g_BP1  [4 * 512 * 64];   // [We1_top | We1_mid]
__device__ __align__(16) __nv_bfloat16 g_We1eP[256 * 64];       // We1 edge rows (K=32)
__device__ __align__(16) __nv_bfloat16 g_We2P [8 * 128 * 64];
__device__ __align__(16) __nv_bfloat16 g_Wn1P [8 * 256 * 64];
__device__ __align__(16) __nv_bfloat16 g_Wn2P [8 * 128 * 64];

__device__ __forceinline__ float swish_fast(float x) {
    float e = __expf(-x);
    return x * __fdividef(1.f, 1.f + e);
}

// single-MUFU swish: sigmoid(x) = 0.5*tanh(x/2) + 0.5
__device__ __forceinline__ float swish_tanh(float x) {
    float t;
    asm("tanh.approx.f32 %0, %1;" : "=f"(t) : "f"(x * 0.5f));
    return x * fmaf(t, 0.5f, 0.5f);
}

// ---------------- common asm helpers -----------------------------------------
__device__ __forceinline__ void mma_bf16(float (&c)[4],
                                         unsigned a0, unsigned a1, unsigned a2, unsigned a3,
                                         unsigned b0, unsigned b1) {
    asm volatile(
        "mma.sync.aligned.m16n8k16.row.col.f32.bf16.bf16.f32 "
        "{%0,%1,%2,%3}, {%4,%5,%6,%7}, {%8,%9}, {%0,%1,%2,%3};"
        : "+f"(c[0]), "+f"(c[1]), "+f"(c[2]), "+f"(c[3])
        : "r"(a0), "r"(a1), "r"(a2), "r"(a3), "r"(b0), "r"(b1));
}

__device__ __forceinline__ void ldsm4(unsigned& r0, unsigned& r1, unsigned& r2, unsigned& r3,
                                      unsigned addr) {
    asm volatile("ldmatrix.sync.aligned.m8n8.x4.shared.b16 {%0,%1,%2,%3}, [%4];"
                 : "=r"(r0), "=r"(r1), "=r"(r2), "=r"(r3) : "r"(addr));
}

#define CP16(dst, src) asm volatile("cp.async.cg.shared.global [%0], [%1], 16;" :: "r"(dst), "l"(src))
#define CPCOMMIT()     asm volatile("cp.async.commit_group;" ::: "memory")
#define CPWAIT1()      asm volatile("cp.async.wait_group 1;" ::: "memory")
#define CPWAIT0()      asm volatile("cp.async.wait_group 0;" ::: "memory")

// split 32 fp32 -> 32 hi + 32 lo bf16, store 128B at dst (16B aligned)
__device__ __forceinline__ void split_store32(const float* x, __nv_bfloat16* dst) {
    unsigned hw[16], lw[16];
    #pragma unroll
    for (int t = 0; t < 16; ++t) {
        __nv_bfloat162 h = __floats2bfloat162_rn(x[2*t], x[2*t+1]);
        __nv_bfloat162 l = __floats2bfloat162_rn(x[2*t]   - __bfloat162float(h.x),
                                                 x[2*t+1] - __bfloat162float(h.y));
        hw[t] = *(unsigned*)&h;
        lw[t] = *(unsigned*)&l;
    }
    uint4* dh = (uint4*)dst;
    uint4* dl = (uint4*)(dst + 32);
    #pragma unroll
    for (int t = 0; t < 4; ++t) {
        dh[t] = make_uint4(hw[4*t], hw[4*t+1], hw[4*t+2], hw[4*t+3]);
        dl[t] = make_uint4(lw[4*t], lw[4*t+1], lw[4*t+2], lw[4*t+3]);
    }
}

// ============================================================================
// Packed GEMM: CTA tile 64(M)x128(N), K-chunks of 32, 256 threads (8 warps 2x4)
// stage: Ah[64][40] Al Bh[128][40] Bl; 80B rows (cf-free ldmatrix), 30720B
// 3-stage ring, 2 CTAs/SM (measured better than 2-stage/3-CTA in R8 vs R13).
// ============================================================================
#define GSTAGE 30720
#define GSMEM  (3 * GSTAGE)      // 92160

__device__ __forceinline__ void g_ldstage(
    const __nv_bfloat16* __restrict__ AP0, const __nv_bfloat16* __restrict__ AP1,
    int splitAt, const __nv_bfloat16* __restrict__ BP, int NBW, int n0,
    int m0, int kc, unsigned smst, int tid)
{
    const __nv_bfloat16* AP = (kc < splitAt) ? AP0 : AP1;
    const int kcl = (kc < splitAt) ? kc : kc - splitAt;
    {
        const int r = tid >> 2, seg = (tid & 3) * 16;
        const char* srcA = (const char*)(AP + ((size_t)kcl * N_PAD + (m0 + r)) * 64);
        CP16(smst + r * 80 + seg,        srcA + seg);
        CP16(smst + 5120 + r * 80 + seg, srcA + 64 + seg);
    }
    {
        const int n = tid >> 1, s0 = (tid & 1) * 32;
        const char* srcB = (const char*)(BP + ((size_t)kc * NBW + n0 + n) * 64);
        CP16(smst + 10240 + n * 80 + s0,      srcB + s0);
        CP16(smst + 10240 + n * 80 + s0 + 16, srcB + s0 + 16);
        CP16(smst + 20480 + n * 80 + s0,      srcB + 64 + s0);
        CP16(smst + 20480 + n * 80 + s0 + 16, srcB + 64 + s0 + 16);
    }
}

// 3-term split mma on a stage (A hi/lo @ st, st+5120; B hi/lo @ st+10240, st+20480)
__device__ __forceinline__ void g_mma(unsigned st, float (&C)[2][4][4],
                                      int wm, int wn, int lane)
{
    const unsigned aH = st, aL = st + 5120, bH = st + 10240, bL = st + 20480;
    const unsigned aoff = (unsigned)((wm * 32 + (lane & 15)) * 80 + (lane >> 4) * 16);
    const unsigned boff = (unsigned)((wn * 32 + ((lane >> 4) & 1) * 8 + (lane & 7)) * 80
                                     + ((lane >> 3) & 1) * 16);
    #pragma unroll
    for (int ks = 0; ks < 2; ++ks) {
        const unsigned kb = ks * 32;
        unsigned ah[2][4], al[2][4];
        #pragma unroll
        for (int mf = 0; mf < 2; ++mf) {
            ldsm4(ah[mf][0], ah[mf][1], ah[mf][2], ah[mf][3], aH + aoff + mf * 16 * 80 + kb);
            ldsm4(al[mf][0], al[mf][1], al[mf][2], al[mf][3], aL + aoff + mf * 16 * 80 + kb);
        }
        #pragma unroll
        for (int p = 0; p < 2; ++p) {
            unsigned bh[4], bl[4];
            ldsm4(bh[0], bh[1], bh[2], bh[3], bH + boff + p * 16 * 80 + kb);
            ldsm4(bl[0], bl[1], bl[2], bl[3], bL + boff + p * 16 * 80 + kb);
            #pragma unroll
            for (int sub = 0; sub < 2; ++sub) {
                int nf = p * 2 + sub;
                unsigned b0h = bh[sub * 2], b1h = bh[sub * 2 + 1];
                unsigned b0l = bl[sub * 2], b1l = bl[sub * 2 + 1];
                #pragma unroll
                for (int mf = 0; mf < 2; ++mf) {
                    mma_bf16(C[mf][nf], ah[mf][0], ah[mf][1], ah[mf][2], ah[mf][3], b0h, b1h);
                    mma_bf16(C[mf][nf], ah[mf][0], ah[mf][1], ah[mf][2], ah[mf][3], b0l, b1l);
                    mma_bf16(C[mf][nf], al[mf][0], al[mf][1], al[mf][2], al[mf][3], b0h, b1h);
                }
            }
        }
    }
}

// 3-stage ring pipeline (one sync per chunk)
__device__ __forceinline__ void gemm_run(
    const __nv_bfloat16* __restrict__ AP0, const __nv_bfloat16* __restrict__ AP1,
    int splitAt, const __nv_bfloat16* __restrict__ BP, int NBW, int n0,
    int m0, int KT, unsigned smb, float (&C)[2][4][4],
    int tid, int wm, int wn, int lane)
{
    g_ldstage(AP0, AP1, splitAt, BP, NBW, n0, m0, 0, smb, tid);          CPCOMMIT();
    g_ldstage(AP0, AP1, splitAt, BP, NBW, n0, m0, 1, smb + GSTAGE, tid); CPCOMMIT();
    for (int kc = 0; kc < KT; ++kc) {
        if (kc < KT - 1) CPWAIT1(); else CPWAIT0();
        __syncthreads();
        if (kc + 2 < KT) {
            g_ldstage(AP0, AP1, splitAt, BP, NBW, n0, m0, kc + 2,
                      smb + (unsigned)((kc + 2) % 3) * GSTAGE, tid);
            CPCOMMIT();
        }
        g_mma(smb + (unsigned)(kc % 3) * GSTAGE, C, wm, wn, lane);
    }
}

__device__ __forceinline__ void stage_C(float (&C)[2][4][4], float* lnbuf,
                                        int wm, int wn, int lane)
{
    const int gr = lane >> 2, tc = lane & 3;
    #pragma unroll
    for (int mf = 0; mf < 2; ++mf) {
        int lr = wm * 32 + mf * 16 + gr;
        #pragma unroll
        for (int nf = 0; nf < 4; ++nf) {
            int col = wn * 32 + nf * 8 + 2 * tc;
            *(float2*)&lnbuf[lr * 132 + col]       = make_float2(C[mf][nf][0], C[mf][nf][1]);
            *(float2*)&lnbuf[(lr + 8) * 132 + col] = make_float2(C[mf][nf][2], C[mf][nf][3]);
        }
    }
}

#define GEMM_HEAD()                                                            \
    extern __shared__ __align__(16) char sm[];                                 \
    const unsigned smb = (unsigned)__cvta_generic_to_shared(sm);               \
    const int tid = threadIdx.x;                                               \
    const int w = tid >> 5, lane = tid & 31;                                   \
    const int wm = w & 1, wn = w >> 1;                                         \
    const int m0 = blockIdx.x * 64;                                            \
    float C[2][4][4];                                                          \
    _Pragma("unroll") for (int mf = 0; mf < 2; ++mf)                           \
        _Pragma("unroll") for (int nf = 0; nf < 4; ++nf)                       \
            _Pragma("unroll") for (int i = 0; i < 4; ++i) C[mf][nf][i] = 0.f;

// ---------------------------------------------------------------------------
// K_PACK: blocks [0,25): weights -> packed layout; blocks [25,807): node rows.
// ---------------------------------------------------------------------------
__global__ __launch_bounds__(256) void k_pack(
    const float* __restrict__ node,
    const float* __restrict__ We1, const float* __restrict__ We2,
    const float* __restrict__ Wn1, const float* __restrict__ Wn2)
{
    if (blockIdx.x < 25) {
        int idx = blockIdx.x * 256 + threadIdx.x;
        float v[32];
        __nv_bfloat16* dst;
        if (idx < 2048) {                               // BP1: [4][512]
            int kc = idx >> 9, n = idx & 511;
            int rb = (n < 256) ? kc * 32 : 128 + kc * 32;
            int c = n & 255;
            #pragma unroll
            for (int k = 0; k < 32; ++k) v[k] = We1[(rb + k) * 256 + c];
            dst = g_BP1 + (size_t)idx * 64;
        } else if (idx < 2304) {                        // We1eP: [256]
            int n = idx - 2048;
            #pragma unroll
            for (int k = 0; k < 32; ++k) v[k] = We1[(256 + k) * 256 + n];
            dst = g_We1eP + (size_t)n * 64;
        } else if (idx < 3328) {                        // We2P: [8][128]
            int t = idx - 2304, kc = t >> 7, n = t & 127;
            #pragma unroll
            for (int k = 0; k < 32; ++k) v[k] = We2[(kc * 32 + k) * 128 + n];
            dst = g_We2P + (size_t)t * 64;
        } else if (idx < 5376) {                        // Wn1P: [8][256]
            int t = idx - 3328, kc = t >> 8, n = t & 255;
            #pragma unroll
            for (int k = 0; k < 32; ++k) v[k] = Wn1[(kc * 32 + k) * 256 + n];
            dst = g_Wn1P + (size_t)t * 64;
        } else if (idx < 6400) {                        // Wn2P: [8][128]
            int t = idx - 5376, kc = t >> 7, n = t & 127;
            #pragma unroll
            for (int k = 0; k < 32; ++k) v[k] = Wn2[(kc * 32 + k) * 128 + n];
            dst = g_Wn2P + (size_t)t * 64;
        } else return;
        split_store32(v, dst);
    } else {
        int r = (blockIdx.x - 25) * 64 + ((int)threadIdx.x >> 2);
        int part = threadIdx.x & 3;
        if (r >= N_NODES) return;
        const float* src = node + (size_t)r * DIM + part * 32;
        float v[32];
        #pragma unroll
        for (int q = 0; q < 8; ++q) *(float4*)&v[4 * q] = ((const float4*)src)[q];
        split_store32(v, g_nodeP + ((size_t)part * N_PAD + r) * 64);
    }
}

// ---------------------------------------------------------------------------
// K1: S(bf16) = node@We1[0:128,:], R(fp32) = node@We1[128:256,:] + be1. grid (782,4)
// ---------------------------------------------------------------------------
__global__ __launch_bounds__(256, 2) void k1_g(const float* __restrict__ be1)
{
    GEMM_HEAD();
    const int n0g = blockIdx.y * 128;
    gemm_run(g_nodeP, g_nodeP, 4, g_BP1, 512, n0g, m0, 4, smb, C, tid, wm, wn, lane);

    const int gr = lane >> 2, tc = lane & 3;
    #pragma unroll
    for (int mf = 0; mf < 2; ++mf) {
        int row = m0 + wm * 32 + mf * 16 + gr;
        #pragma unroll
        for (int nf = 0; nf < 4; ++nf) {
            int gcol = n0g + wn * 32 + nf * 8 + 2 * tc;
            int which = gcol >> 8;
            int col = gcol & 255;
            if (which == 0) {
                __nv_bfloat162 t0 = __floats2bfloat162_rn(C[mf][nf][0], C[mf][nf][1]);
                __nv_bfloat162 t1 = __floats2bfloat162_rn(C[mf][nf][2], C[mf][nf][3]);
                if (row < N_NODES)
                    *(unsigned*)(g_Sb + (size_t)row * HID + col) = *(unsigned*)&t0;
                if (row + 8 < N_NODES)
                    *(unsigned*)(g_Sb + (size_t)(row + 8) * HID + col) = *(unsigned*)&t1;
            } else {
                float b0 = be1[col], b1 = be1[col + 1];
                if (row < N_NODES)
                    *(float2*)(g_R + (size_t)row * HID + col) =
                        make_float2(C[mf][nf][0] + b0, C[mf][nf][1] + b1);
                if (row + 8 < N_NODES)
                    *(float2*)(g_R + (size_t)(row + 8) * HID + col) =
                        make_float2(C[mf][nf][2] + b0, C[mf][nf][3] + b1);
            }
        }
    }
}

// ---------------------------------------------------------------------------
// K3: aggln = LN(Hagg @ We2 / 16 + be2) * mask -> packed agglnP.  grid (782)
// ---------------------------------------------------------------------------
__global__ __launch_bounds__(256, 2) void k3_g(
    const float* __restrict__ be2, const float* __restrict__ gmsg,
    const float* __restrict__ bmsg, const float* __restrict__ mask)
{
    GEMM_HEAD();
    gemm_run(g_HaggP, g_HaggP, 8, g_We2P, 128, 0, m0, 8, smb, C, tid, wm, wn, lane);
    __syncthreads();
    float* lnbuf = (float*)sm;
    stage_C(C, lnbuf, wm, wn, lane);
    __syncthreads();

    const int r = tid >> 2, part = tid & 3;
    const int grow = m0 + r;
    float x[32], s = 0.f, ss = 0.f;
    #pragma unroll
    for (int j = 0; j < 32; ++j) {
        int col = part * 32 + j;
        float t = lnbuf[r * 132 + col] * (1.f / DEG) + be2[col];
        x[j] = t; s += t; ss += t * t;
    }
    s  += __shfl_xor_sync(~0u, s, 1);  s  += __shfl_xor_sync(~0u, s, 2);
    ss += __shfl_xor_sync(~0u, ss, 1); ss += __shfl_xor_sync(~0u, ss, 2);
    float mean = s * (1.f / 128.f);
    float var  = ss * (1.f / 128.f) - mean * mean;
    float inv  = rsqrtf(var + EPS);
    if (grow < N_NODES) {
        float mk = mask[grow];
        float y[32];
        #pragma unroll
        for (int j = 0; j < 32; ++j) {
            int col = part * 32 + j;
            y[j] = ((x[j] - mean) * inv * gmsg[col] + bmsg[col]) * mk;
        }
        split_store32(y, g_agglnP + ((size_t)part * N_PAD + grow) * 64);
    }
}

// ---------------------------------------------------------------------------
// K4a: H = swish([node | aggln] @ Wn1 + bn1) -> packed HP.  grid (782, 2)
// ---------------------------------------------------------------------------
__global__ __launch_bounds__(256, 2) void k4a_g(const float* __restrict__ bn1)
{
    GEMM_HEAD();
    const int n0g = blockIdx.y * 128;
    gemm_run(g_nodeP, g_agglnP, 4, g_Wn1P, 256, n0g, m0, 8, smb, C, tid, wm, wn, lane);
    __syncthreads();
    float* lnbuf = (float*)sm;
    stage_C(C, lnbuf, wm, wn, lane);
    __syncthreads();

    const int r = tid >> 2, part = tid & 3;
    const int grow = m0 + r;
    if (grow < N_NODES) {
        float y[32];
        #pragma unroll
        for (int j = 0; j < 32; ++j) {
            int col = part * 32 + j;
            y[j] = swish_fast(lnbuf[r * 132 + col] + bn1[n0g + col]);
        }
        split_store32(y, g_HP + ((size_t)((n0g >> 5) + part) * N_PAD + grow) * 64);
    }
}

// ---------------------------------------------------------------------------
// K4b: out = LN(H @ Wn2 + bn2 + node) * mask.  grid (782)
// ---------------------------------------------------------------------------
__global__ __launch_bounds__(256, 2) void k4b_g(
    const float* __restrict__ node, const float* __restrict__ bn2,
    const float* __restrict__ gnode, const float* __restrict__ bnode,
    const float* __restrict__ mask, float* __restrict__ out)
{
    GEMM_HEAD();
    gemm_run(g_HP, g_HP, 8, g_Wn2P, 128, 0, m0, 8, smb, C, tid, wm, wn, lane);
    __syncthreads();
    float* lnbuf = (float*)sm;
    stage_C(C, lnbuf, wm, wn, lane);
    __syncthreads();

    const int r = tid >> 2, part = tid & 3;
    const int grow = m0 + r;
    float x[32], s = 0.f, ss = 0.f;
    #pragma unroll
    for (int j = 0; j < 32; ++j) {
        int col = part * 32 + j;
        float res = (grow < N_NODES) ? node[(size_t)grow * DIM + col] : 0.f;
        float t = lnbuf[r * 132 + col] + bn2[col] + res;
        x[j] = t; s += t; ss += t * t;
    }
    s  += __shfl_xor_sync(~0u, s, 1);  s  += __shfl_xor_sync(~0u, s, 2);
    ss += __shfl_xor_sync(~0u, ss, 1); ss += __shfl_xor_sync(~0u, ss, 2);
    float mean = s * (1.f / 128.f);
    float var  = ss * (1.f / 128.f) - mean * mean;
    float inv  = rsqrtf(var + EPS);
    if (grow < N_NODES) {
        float mk = mask[grow];
        float* op = out + (size_t)grow * DIM + part * 32;
        #pragma unroll
        for (int q = 0; q < 8; ++q) {
            float4 o;
            int j = 4 * q, col = part * 32 + j;
            o.x = ((x[j]     - mean) * inv * gnode[col]     + bnode[col])     * mk;
            o.y = ((x[j + 1] - mean) * inv * gnode[col + 1] + bnode[col + 1]) * mk;
            o.z = ((x[j + 2] - mean) * inv * gnode[col + 2] + bnode[col + 2]) * mk;
            o.w = ((x[j + 3] - mean) * inv * gnode[col + 3] + bnode[col + 3]) * mk;
            *(float4*)(op + j) = o;
        }
    }
}

// ============================================================================
// K2F v6: 256 edges/CTA, single-term bf16 MMA, bf16 EP buffer, bf16 S gather.
// grid (3125, 2), 256 thr, 4 CTAs/SM.
// smem: Bh @0 (10240), Ah @10240 (5120), EP bf16x2 @15360 (64 x 68 words)
// ============================================================================
#define K2_B    0
#define K2_A    10240
#define K2_EP   15360
#define K2_SMEM 32768

__device__ __forceinline__ void k2_store_A(char* sm, const float* __restrict__ edge_feat,
                                           int ebase, int tid)
{
    __nv_bfloat16* Ah = (__nv_bfloat16*)(sm + K2_A);
    const int r = tid >> 2, c8 = (tid & 3) * 8;
    const float4* src = (const float4*)(edge_feat + (size_t)(ebase + r) * EDIM + c8);
    float4 f0 = src[0], f1 = src[1];
    __nv_bfloat162 h0 = __floats2bfloat162_rn(f0.x, f0.y);
    __nv_bfloat162 h1 = __floats2bfloat162_rn(f0.z, f0.w);
    __nv_bfloat162 h2 = __floats2bfloat162_rn(f1.x, f1.y);
    __nv_bfloat162 h3 = __floats2bfloat162_rn(f1.z, f1.w);
    *(uint4*)(Ah + r * 40 + c8) = make_uint4(*(unsigned*)&h0, *(unsigned*)&h1,
                                             *(unsigned*)&h2, *(unsigned*)&h3);
}

// single-term mma: A hi @ aBase, B hi @ bBase
__device__ __forceinline__ void g_mma1(unsigned aBase, unsigned bBase,
                                       float (&C)[2][4][4], int wm, int wn, int lane)
{
    const unsigned aoff = (unsigned)((wm * 32 + (lane & 15)) * 80 + (lane >> 4) * 16);
    const unsigned boff = (unsigned)((wn * 32 + ((lane >> 4) & 1) * 8 + (lane & 7)) * 80
                                     + ((lane >> 3) & 1) * 16);
    #pragma unroll
    for (int ks = 0; ks < 2; ++ks) {
        const unsigned kb = ks * 32;
        unsigned ah[2][4];
        #pragma unroll
        for (int mf = 0; mf < 2; ++mf)
            ldsm4(ah[mf][0], ah[mf][1], ah[mf][2], ah[mf][3],
                  aBase + aoff + mf * 16 * 80 + kb);
        #pragma unroll
        for (int p = 0; p < 2; ++p) {
            unsigned bh[4];
            ldsm4(bh[0], bh[1], bh[2], bh[3], bBase + boff + p * 16 * 80 + kb);
            #pragma unroll
            for (int sub = 0; sub < 2; ++sub) {
                int nf = p * 2 + sub;
                #pragma unroll
                for (int mf = 0; mf < 2; ++mf)
                    mma_bf16(C[mf][nf], ah[mf][0], ah[mf][1], ah[mf][2], ah[mf][3],
                             bh[sub * 2], bh[sub * 2 + 1]);
            }
        }
    }
}

// C -> bf16x2 EP buffer, stride 68 words (banks 4*gr+tc: conflict-free)
__device__ __forceinline__ void stage_C_bf16(float (&C)[2][4][4], unsigned* EPw,
                                             int wm, int wn, int lane)
{
    const int gr = lane >> 2, tc = lane & 3;
    #pragma unroll
    for (int mf = 0; mf < 2; ++mf) {
        int lr = wm * 32 + mf * 16 + gr;
        #pragma unroll
        for (int nf = 0; nf < 4; ++nf) {
            int wrd = wn * 16 + nf * 4 + tc;
            __nv_bfloat162 a = __floats2bfloat162_rn(C[mf][nf][0], C[mf][nf][1]);
            __nv_bfloat162 b = __floats2bfloat162_rn(C[mf][nf][2], C[mf][nf][3]);
            EPw[lr * 68 + wrd]       = *(unsigned*)&a;
            EPw[(lr + 8) * 68 + wrd] = *(unsigned*)&b;
        }
    }
}

__global__ __launch_bounds__(256, 4) void k2f(
    const float* __restrict__ edge_feat, const int* __restrict__ senders)
{
    extern __shared__ __align__(16) char sm[];
    __shared__ int ss[256];
    const unsigned smb = (unsigned)__cvta_generic_to_shared(sm);
    const int tid = threadIdx.x;
    const int w = tid >> 5, lane = tid & 31;
    const int wm = w & 1, wn = w >> 1;

    const int e0 = blockIdx.x * 256;
    const int n0 = blockIdx.y * 128;

    // B hi: stage once (first 64B of each packed We1eP row)
    {
        const int n = tid >> 1, h = (tid & 1) * 32;
        const char* srcB = (const char*)(g_We1eP + (size_t)(n0 + n) * 64);
        CP16(smb + K2_B + n * 80 + h,      srcB + h);
        CP16(smb + K2_B + n * 80 + h + 16, srcB + h + 16);
        CPCOMMIT();
    }
    ss[tid] = senders[e0 + tid];
    k2_store_A(sm, edge_feat, e0, tid);
    CPWAIT0();
    __syncthreads();

    unsigned* EPw = (unsigned*)(sm + K2_EP);
    const int node_l = w >> 1;                 // 0..3 within the 64-edge round
    const int ch = w & 1;
    const int co = ch * 64 + lane * 2;         // 0..126
    const __nv_bfloat16* Sbase = g_Sb + n0 + co;

    #pragma unroll
    for (int g = 0; g < 4; ++g) {
        float C[2][4][4];
        #pragma unroll
        for (int mf = 0; mf < 2; ++mf)
            #pragma unroll
            for (int nf = 0; nf < 4; ++nf)
                #pragma unroll
                for (int i = 0; i < 4; ++i) C[mf][nf][i] = 0.f;

        g_mma1(smb + K2_A, smb + K2_B, C, wm, wn, lane);
        stage_C_bf16(C, EPw, wm, wn, lane);
        __syncthreads();                       // EP ready; A reads done

        if (g < 3) k2_store_A(sm, edge_feat, e0 + (g + 1) * 64, tid);

        // epilogue: warp-per-(node, col-half), coalesced bf16 S gather
        const int node_g = (e0 >> 4) + g * 4 + node_l;
        const float2 rr = *(const float2*)(g_R + (size_t)node_g * HID + n0 + co);
        float a0 = 0.f, a1 = 0.f;
        #pragma unroll
        for (int e = 0; e < 16; ++e) {
            int snd = ss[g * 64 + node_l * 16 + e];
            unsigned svu = *(const unsigned*)(Sbase + (unsigned)(snd * HID));
            __nv_bfloat162 sv = *(__nv_bfloat162*)&svu;
            unsigned epu = EPw[(node_l * 16 + e) * 68 + ch * 32 + lane];
            __nv_bfloat162 ep = *(__nv_bfloat162*)&epu;
            a0 += swish_tanh(__bfloat162float(ep.x) + __bfloat162float(sv.x) + rr.x);
            a1 += swish_tanh(__bfloat162float(ep.y) + __bfloat162float(sv.y) + rr.y);
        }
        {
            int gcol = n0 + co;
            int kc = gcol >> 5, kin = gcol & 31;
            size_t base = ((size_t)kc * N_PAD + node_g) * 64 + kin;
            __nv_bfloat162 hh = __floats2bfloat162_rn(a0, a1);
            __nv_bfloat162 ll = __floats2bfloat162_rn(a0 - __bfloat162float(hh.x),
                                                      a1 - __bfloat162float(hh.y));
            *(unsigned*)&g_HaggP[base]      = *(unsigned*)&hh;
            *(unsigned*)&g_HaggP[base + 32] = *(unsigned*)&ll;
        }
        if (g < 3) __syncthreads();            // A staged + EP reads done before next round
    }
}

// ---------------------------------------------------------------------------
extern "C" void kernel_launch(void* const* d_in, const int* in_sizes, int n_in,
                              void* d_out, int out_size)
{
    const float* node      = (const float*)d_in[0];
    const float* edge_feat = (const float*)d_in[1];
    const float* mask      = (const float*)d_in[2];
    const float* We1       = (const float*)d_in[3];
    const float* be1       = (const float*)d_in[4];
    const float* We2       = (const float*)d_in[5];
    const float* be2       = (const float*)d_in[6];
    const float* gmsg      = (const float*)d_in[7];
    const float* bmsg      = (const float*)d_in[8];
    const float* Wn1       = (const float*)d_in[9];
    const float* bn1       = (const float*)d_in[10];
    const float* Wn2       = (const float*)d_in[11];
    const float* bn2       = (const float*)d_in[12];
    const float* gnode     = (const float*)d_in[13];
    const float* bnode     = (const float*)d_in[14];
    const int*   senders   = (const int*)d_in[15];
    float* out = (float*)d_out;

    cudaFuncSetAttribute(k1_g,  cudaFuncAttributeMaxDynamicSharedMemorySize, GSMEM);
    cudaFuncSetAttribute(k2f,   cudaFuncAttributeMaxDynamicSharedMemorySize, K2_SMEM);
    cudaFuncSetAttribute(k3_g,  cudaFuncAttributeMaxDynamicSharedMemorySize, GSMEM);
    cudaFuncSetAttribute(k4a_g, cudaFuncAttributeMaxDynamicSharedMemorySize, GSMEM);
    cudaFuncSetAttribute(k4b_g, cudaFuncAttributeMaxDynamicSharedMemorySize, GSMEM);

    const int mb = N_PAD / 64;   // 782

    k_pack<<<25 + mb, 256>>>(node, We1, We2, Wn1, Wn2);
    k1_g  <<<dim3(mb, 4), 256, GSMEM>>>(be1);
    k2f   <<<dim3(E_EDGES / 256, 2), 256, K2_SMEM>>>(edge_feat, senders);
    k3_g  <<<mb, 256, GSMEM>>>(be2, gmsg, bmsg, mask);
    k4a_g <<<dim3(mb, 2), 256, GSMEM>>>(bn1);
    k4b_g <<<mb, 256, GSMEM>>>(node, bn2, gnode, bnode, mask, out);
}